// round 10
// baseline (speedup 1.0000x reference)
#include <cuda_runtime.h>
#include <cuda_bf16.h>
#include <math.h>
#include <stdint.h>

#define Bn 32
#define Sn 2048
#define NCHUNK 16
#define NTILES 1024          // 64-row tiles over 65536 rows
#define K1_GRID 148
#define K1_THREADS 256

// ------------------------------ device scratch ------------------------------
__device__ float g_D[Bn * 512];
__device__ float g_scores[Bn * Sn];
__device__ float g_weights[Bn * Sn];
__device__ float g_partial[Bn * NCHUNK * 1024];
// W_enc staged as bf16 hi/lo, 64B-row-swizzled [n][k] pieces.
// 32 pieces (kc 0..31), each 64KB = [hi 32KB][lo 32KB]; rows n=0..511, 32 k
__device__ __align__(16) unsigned char g_Bt[32 * 65536];

// ------------------------------ helpers -------------------------------------
__device__ __forceinline__ uint32_t smem_u32(const void* p) {
    uint32_t a;
    asm("{ .reg .u64 t; cvta.to.shared.u64 t, %1; cvt.u32.u64 %0, t; }"
        : "=r"(a) : "l"(p));
    return a;
}
__device__ __forceinline__ uint32_t swz64(uint32_t off) {
    return off ^ ((off >> 3) & 0x30);
}
__device__ __forceinline__ void ldsm4(uint32_t* r, uint32_t addr) {
    asm volatile("ldmatrix.sync.aligned.m8n8.x4.shared.b16 {%0,%1,%2,%3}, [%4];"
                 : "=r"(r[0]), "=r"(r[1]), "=r"(r[2]), "=r"(r[3]) : "r"(addr));
}
__device__ __forceinline__ void mma_bf16(float* c, const uint32_t* a,
                                         uint32_t b0, uint32_t b1) {
    asm("mma.sync.aligned.m16n8k16.row.col.f32.bf16.bf16.f32 "
        "{%0,%1,%2,%3},{%4,%5,%6,%7},{%8,%9},{%0,%1,%2,%3};"
        : "+f"(c[0]), "+f"(c[1]), "+f"(c[2]), "+f"(c[3])
        : "r"(a[0]), "r"(a[1]), "r"(a[2]), "r"(a[3]), "r"(b0), "r"(b1));
}
__device__ __forceinline__ void cp16(uint32_t dst, const void* src) {
    asm volatile("cp.async.cg.shared.global [%0], [%1], 16;"
                 :: "r"(dst), "l"(src));
}
__device__ __forceinline__ void cp_commit() {
    asm volatile("cp.async.commit_group;" ::: "memory");
}
__device__ __forceinline__ void cp_wait1() {
    asm volatile("cp.async.wait_group 1;" ::: "memory");
}
__device__ __forceinline__ void cp_wait0() {
    asm volatile("cp.async.wait_group 0;" ::: "memory");
}

// ------------------------------ k0: decoder att -----------------------------
__global__ void k0_decoder(const float* __restrict__ dec,
                           const float* __restrict__ Wd,
                           const float* __restrict__ bd,
                           const float* __restrict__ be) {
    int b = blockIdx.x, ah = blockIdx.y, t = threadIdx.x;
    __shared__ float ds[512];
    ds[t]       = dec[b * 512 + t];
    ds[t + 256] = dec[b * 512 + t + 256];
    __syncthreads();
    int a = ah * 256 + t;
    float acc = be[a] + bd[a];
#pragma unroll 8
    for (int h = 0; h < 512; h++) acc += ds[h] * Wd[h * 512 + a];
    g_D[b * 512 + a] = acc;
}

// ------------------------------ kW: stage W_enc -----------------------------
// piece kc: [n 0..511][k 0..31], 64B rows, swz64; hi plane +0, lo +32KB
__global__ void kW_convert(const float* __restrict__ We) {
    int gid = blockIdx.x * 256 + threadIdx.x;   // 0..524287
    int k = gid >> 9, n = gid & 511;
    float w = We[gid];
    __nv_bfloat16 hi = __float2bfloat16(w);
    float rem = w - __bfloat162float(hi);
    __nv_bfloat16 lo = __float2bfloat16(rem);
    int kc = k >> 5, kl = k & 31;
    uint32_t sw = swz64((uint32_t)n * 64u + (uint32_t)kl * 2u);
    unsigned char* basep = g_Bt + (size_t)kc * 65536;
    *(__nv_bfloat16*)(basep + sw)         = hi;
    *(__nv_bfloat16*)(basep + 32768 + sw) = lo;
}

// ------------------------------ K1: persistent HMMA scores ------------------
// stage = A 8KB (hi4K+lo4K) + B 64KB (hi32K+lo32K) = 72KB; ring of 3 = 216KB
#define SA_PLANE 4096
#define SB_PLANE 32768
#define SA_OFF 0
#define SB_OFF 8192
#define STAGE  73728
#define SM_SMEM (3 * STAGE)

__global__ __launch_bounds__(K1_THREADS)
void k1_mma(const float* __restrict__ enc,
            const float* __restrict__ Wa,
            const float* __restrict__ ba) {
    extern __shared__ char smem[];
    __shared__ float s_sc[64];
    const uint32_t sb = smem_u32(smem);
    const int tid = threadIdx.x;
    const int wid = tid >> 5, lid = tid & 31;
    const int bid = blockIdx.x;
    const int wm = wid & 1;            // rows wm*32..+32
    const int wn = wid >> 1;           // cols wn*128..+128
    const int r4 = lid >> 2, q = lid & 3;

    const uint32_t aoffb = (uint32_t)(wm * 32 + (lid & 15)) * 64u + ((lid >> 4) * 16u);
    const uint32_t boffb = (uint32_t)((lid & 7) + ((lid >> 4) << 3)) * 64u +
                           (((lid >> 3) & 1) * 16u);

    const int ntiles = (NTILES - bid + K1_GRID - 1) / K1_GRID;
    const int nsteps = ntiles * 32;    // 32 k-chunks per tile

    float4 ar[2][2];                   // two in-flight A reg sets

    auto ldgA = [&](int s) {
        int t_ = s >> 5, kc = s & 31;
        int r0 = (bid + t_ * K1_GRID) * 64;
        const float4* src = (const float4*)(enc + (size_t)r0 * 1024 + kc * 32);
#pragma unroll
        for (int v = 0; v < 2; v++) {
            int idx = v * 256 + tid;       // 0..511 float4s
            int row = idx >> 3, kq = idx & 7;
            ar[s & 1][v] = src[(size_t)row * 256 + kq];
        }
    };
    auto cpB = [&](int s, int buf) {
        int kc = s & 31;
        const unsigned char* srcB = g_Bt + (size_t)kc * 65536;
        uint32_t dst = sb + buf * STAGE + SB_OFF;
#pragma unroll
        for (int v = 0; v < 16; v++)
            cp16(dst + (v * 256 + tid) * 16, srcB + (size_t)(v * 256 + tid) * 16);
        cp_commit();
    };
    auto stsA = [&](int s, int buf) {
        char* abuf = smem + buf * STAGE + SA_OFF;
#pragma unroll
        for (int v = 0; v < 2; v++) {
            int idx = v * 256 + tid;
            int row = idx >> 3, kq = idx & 7;
            float4 f = ar[s & 1][v];
            __nv_bfloat16 h0 = __float2bfloat16(f.x), h1 = __float2bfloat16(f.y);
            __nv_bfloat16 h2 = __float2bfloat16(f.z), h3 = __float2bfloat16(f.w);
            __nv_bfloat16 l0 = __float2bfloat16(f.x - __bfloat162float(h0));
            __nv_bfloat16 l1 = __float2bfloat16(f.y - __bfloat162float(h1));
            __nv_bfloat16 l2 = __float2bfloat16(f.z - __bfloat162float(h2));
            __nv_bfloat16 l3 = __float2bfloat16(f.w - __bfloat162float(h3));
            __nv_bfloat162 ph0 = __nv_bfloat162(h0, h1), ph1 = __nv_bfloat162(h2, h3);
            __nv_bfloat162 pl0 = __nv_bfloat162(l0, l1), pl1 = __nv_bfloat162(l2, l3);
            uint32_t sw = swz64((uint32_t)row * 64u + (uint32_t)kq * 8u);
            *(uint2*)(abuf + sw)            = make_uint2(*(uint32_t*)&ph0, *(uint32_t*)&ph1);
            *(uint2*)(abuf + SA_PLANE + sw) = make_uint2(*(uint32_t*)&pl0, *(uint32_t*)&pl1);
        }
    };

    float acc[2][16][4];
#pragma unroll
    for (int mt = 0; mt < 2; mt++)
#pragma unroll
        for (int nt = 0; nt < 16; nt++)
#pragma unroll
            for (int v = 0; v < 4; v++) acc[mt][nt][v] = 0.f;

    // prologue: A(0),B(0) and A(1),B(1); STS A(0)
    ldgA(0); cpB(0, 0);
    ldgA(1); cpB(1, 1);
    stsA(0, 0);

    for (int s = 0; s < nsteps; s++) {
        const int kc = s & 31;
        const int buf = s % 3;

        if (s + 2 < nsteps) cp_wait1(); else cp_wait0();
        __syncthreads();

        if (s + 2 < nsteps) { ldgA(s + 2); cpB(s + 2, (s + 2) % 3); }

        const uint32_t aB = sb + buf * STAGE + SA_OFF;
        const uint32_t bB = sb + buf * STAGE + SB_OFF;

#pragma unroll
        for (int kk = 0; kk < 2; kk++) {
            uint32_t ahf[2][4], alf[2][4];
#pragma unroll
            for (int mt = 0; mt < 2; mt++) {
                uint32_t off = aoffb + (uint32_t)(mt * 16) * 64u + kk * 32u;
                ldsm4(ahf[mt], aB + swz64(off));
                ldsm4(alf[mt], aB + SA_PLANE + swz64(off));
            }
#pragma unroll
            for (int ntp = 0; ntp < 8; ntp++) {
                uint32_t off = boffb + (uint32_t)(wn * 128 + ntp * 16) * 64u + kk * 32u;
                uint32_t bh[4], bl[4];
                ldsm4(bh, bB + swz64(off));
                ldsm4(bl, bB + SB_PLANE + swz64(off));
#pragma unroll
                for (int mt = 0; mt < 2; mt++) {
                    mma_bf16(acc[mt][2 * ntp],     ahf[mt], bh[0], bh[1]);
                    mma_bf16(acc[mt][2 * ntp],     alf[mt], bh[0], bh[1]);
                    mma_bf16(acc[mt][2 * ntp],     ahf[mt], bl[0], bl[1]);
                    mma_bf16(acc[mt][2 * ntp + 1], ahf[mt], bh[2], bh[3]);
                    mma_bf16(acc[mt][2 * ntp + 1], alf[mt], bh[2], bh[3]);
                    mma_bf16(acc[mt][2 * ntp + 1], ahf[mt], bl[2], bl[3]);
                }
            }
        }

        if (kc == 31) {
            // tile epilogue: score = sum_c tanh(acc + D[c]) * Wa[c]
            const int rb = bid + (s >> 5) * K1_GRID;
            const int r0 = rb * 64;
            const int b  = r0 >> 11;
            if (tid < 64) s_sc[tid] = 0.f;
            __syncthreads();
#pragma unroll
            for (int mt = 0; mt < 2; mt++) {
                float p0 = 0.f, p1 = 0.f;
#pragma unroll
                for (int nt = 0; nt < 16; nt++) {
                    int c0 = wn * 128 + nt * 8 + q * 2;
                    float d0v = g_D[b * 512 + c0], d1v = g_D[b * 512 + c0 + 1];
                    float w0 = Wa[c0], w1 = Wa[c0 + 1];
                    p0 += tanhf(acc[mt][nt][0] + d0v) * w0 + tanhf(acc[mt][nt][1] + d1v) * w1;
                    p1 += tanhf(acc[mt][nt][2] + d0v) * w0 + tanhf(acc[mt][nt][3] + d1v) * w1;
                }
                p0 += __shfl_xor_sync(0xffffffffu, p0, 1);
                p0 += __shfl_xor_sync(0xffffffffu, p0, 2);
                p1 += __shfl_xor_sync(0xffffffffu, p1, 1);
                p1 += __shfl_xor_sync(0xffffffffu, p1, 2);
                if (q == 0) {
                    atomicAdd(&s_sc[wm * 32 + mt * 16 + r4], p0);
                    atomicAdd(&s_sc[wm * 32 + mt * 16 + r4 + 8], p1);
                }
            }
            __syncthreads();
            if (tid < 64) g_scores[r0 + tid] = s_sc[tid] + ba[0];
#pragma unroll
            for (int mt = 0; mt < 2; mt++)
#pragma unroll
                for (int nt = 0; nt < 16; nt++)
#pragma unroll
                    for (int v = 0; v < 4; v++) acc[mt][nt][v] = 0.f;
        }

        // convert+store A(s+1) into its buffer (B part arrives via cp.async)
        if (s + 1 < nsteps) stsA(s + 1, (s + 1) % 3);
    }
}

// ------------------------------ k2a: softmax (+mask detect) -----------------
__global__ void k2a_softmax(const unsigned char* __restrict__ masks) {
    int b = blockIdx.x, t = threadIdx.x;
    __shared__ float sm[2048];
    __shared__ float red[256];
    const float NEG_INF = __int_as_float(0xff800000);

    int found = 0;
    for (int j = t; j < 16384; j += 256)
        if (masks[4 * j + 1]) found = 1;
    const int mode = __syncthreads_or(found);   // 1 = byte elems, 0 = 4-byte
    const unsigned int* m32 = (const unsigned int*)masks;

    float lmax = NEG_INF;
#pragma unroll
    for (int v = 0; v < 8; v++) {
        int idx = v * 256 + t;
        float sc = g_scores[b * 2048 + idx];
        bool masked = mode ? (masks[b * 2048 + idx] != 0) : (m32[b * 2048 + idx] != 0u);
        if (masked) sc = NEG_INF;
        sm[idx] = sc;
        lmax = fmaxf(lmax, sc);
    }
    red[t] = lmax;
    __syncthreads();
    for (int o = 128; o > 0; o >>= 1) {
        if (t < o) red[t] = fmaxf(red[t], red[t + o]);
        __syncthreads();
    }
    float bmax = red[0];
    __syncthreads();

    float lsum = 0.f;
#pragma unroll
    for (int v = 0; v < 8; v++) {
        int idx = v * 256 + t;
        float e = expf(sm[idx] - bmax);
        sm[idx] = e;
        lsum += e;
    }
    red[t] = lsum;
    __syncthreads();
    for (int o = 128; o > 0; o >>= 1) {
        if (t < o) red[t] += red[t + o];
        __syncthreads();
    }
    float inv = 1.f / red[0];
#pragma unroll
    for (int v = 0; v < 8; v++) {
        int idx = v * 256 + t;
        g_weights[b * 2048 + idx] = sm[idx] * inv;
    }
}

// ------------------------------ k2b: weighted sum ---------------------------
__global__ void k2b_partial(const float* __restrict__ enc) {
    int ch = blockIdx.x, b = blockIdx.y, t = threadIdx.x;
    __shared__ float w[128];
    if (t < 128) w[t] = g_weights[b * 2048 + ch * 128 + t];
    __syncthreads();

    const float4* rowbase =
        reinterpret_cast<const float4*>(enc) + (size_t)(b * 2048 + ch * 128) * 256;
    float4 acc = make_float4(0.f, 0.f, 0.f, 0.f);
    for (int si = 0; si < 128; si++) {
        float wv = w[si];
        if (wv != 0.f) {
            float4 v = rowbase[(size_t)si * 256 + t];
            acc.x += wv * v.x; acc.y += wv * v.y;
            acc.z += wv * v.z; acc.w += wv * v.w;
        }
    }
    reinterpret_cast<float4*>(g_partial)[(b * NCHUNK + ch) * 256 + t] = acc;
}

// ------------------------------ k2c: final GEMV -----------------------------
__global__ void k2c_context(const float* __restrict__ We,
                            const float* __restrict__ be,
                            float* __restrict__ out) {
    int b = blockIdx.x, t = threadIdx.x;
    __shared__ float ctx[1024];
    float4 s = make_float4(0.f, 0.f, 0.f, 0.f);
#pragma unroll
    for (int chn = 0; chn < NCHUNK; chn++) {
        float4 v = reinterpret_cast<const float4*>(g_partial)[(b * NCHUNK + chn) * 256 + t];
        s.x += v.x; s.y += v.y; s.z += v.z; s.w += v.w;
    }
    reinterpret_cast<float4*>(ctx)[t] = s;
    __syncthreads();

    float acc0 = be[t], acc1 = be[t + 256];
#pragma unroll 4
    for (int k = 0; k < 1024; k++) {
        float c = ctx[k];
        const float* wr = We + k * 512;
        acc0 += c * wr[t];
        acc1 += c * wr[t + 256];
    }
    out[b * 512 + t]       = acc0;
    out[b * 512 + t + 256] = acc1;
}

// ---------------------------------------------------------------------------
extern "C" void kernel_launch(void* const* d_in, const int* in_sizes, int n_in,
                              void* d_out, int out_size) {
    const float*         enc   = (const float*)d_in[0];
    const float*         dec   = (const float*)d_in[1];
    const unsigned char* masks = (const unsigned char*)d_in[2];
    const float*         We    = (const float*)d_in[3];
    const float*         be    = (const float*)d_in[4];
    const float*         Wd    = (const float*)d_in[5];
    const float*         bd    = (const float*)d_in[6];
    const float*         Wa    = (const float*)d_in[7];
    const float*         ba    = (const float*)d_in[8];
    float* out = (float*)d_out;

    static int configured = 0;
    if (!configured) {
        cudaFuncSetAttribute(k1_mma, cudaFuncAttributeMaxDynamicSharedMemorySize, SM_SMEM);
        configured = 1;
    }

    dim3 g0(Bn, 2);
    k0_decoder<<<g0, 256>>>(dec, Wd, bd, be);
    kW_convert<<<2048, 256>>>(We);
    k1_mma<<<K1_GRID, K1_THREADS, SM_SMEM>>>(enc, Wa, ba);
    k2a_softmax<<<Bn, 256>>>(masks);
    dim3 g2b(NCHUNK, Bn);
    k2b_partial<<<g2b, 256>>>(enc);
    k2c_context<<<Bn, 256>>>(We, be, out);
}

// round 11
// speedup vs baseline: 1.1874x; 1.1874x over previous
#include <cuda_runtime.h>
#include <cuda_bf16.h>
#include <math.h>
#include <stdint.h>

#define Bn 32
#define Sn 2048
#define NCHUNK 16
#define NTILES 512           // 128-row tiles
#define NUNITS 1024          // (tile, nc) units
#define K1_GRID 148

// ------------------------------ device scratch ------------------------------
__device__ float g_D[Bn * 512];
__device__ float g_sc2[2][Bn * Sn];     // per-nc score partials
__device__ float g_weights[Bn * Sn];
__device__ float g_partial[Bn * NCHUNK * 1024];
// W_enc staged as bf16 hi/lo, SW128-swizzled [n][k] tiles.
// 32 pieces (nc 0..1 x kc 0..15), each 64KB = [hi 32KB][lo 32KB]
__device__ __align__(16) unsigned char g_Bt[32 * 65536];
// enc staged as bf16 hi/lo, swizzled smem-image pieces.
// piece p = rowblock*16 + kc (rowblock 0..511): 32KB = [hi 16KB][lo 16KB]
__device__ __align__(16) unsigned char g_At[512 * 16 * 32768ull];

// ------------------------------ helpers -------------------------------------
__device__ __forceinline__ uint32_t smem_u32(const void* p) {
    uint32_t a;
    asm("{ .reg .u64 t; cvta.to.shared.u64 t, %1; cvt.u32.u64 %0, t; }"
        : "=r"(a) : "l"(p));
    return a;
}
__device__ __forceinline__ uint32_t swz(uint32_t off) {
    return off ^ ((off >> 3) & 0x70);
}
__device__ __forceinline__ void ldsm4(uint32_t* r, uint32_t addr) {
    asm volatile("ldmatrix.sync.aligned.m8n8.x4.shared.b16 {%0,%1,%2,%3}, [%4];"
                 : "=r"(r[0]), "=r"(r[1]), "=r"(r[2]), "=r"(r[3]) : "r"(addr));
}
__device__ __forceinline__ void mma_bf16(float* c, const uint32_t* a,
                                         uint32_t b0, uint32_t b1) {
    asm("mma.sync.aligned.m16n8k16.row.col.f32.bf16.bf16.f32 "
        "{%0,%1,%2,%3},{%4,%5,%6,%7},{%8,%9},{%0,%1,%2,%3};"
        : "+f"(c[0]), "+f"(c[1]), "+f"(c[2]), "+f"(c[3])
        : "r"(a[0]), "r"(a[1]), "r"(a[2]), "r"(a[3]), "r"(b0), "r"(b1));
}
__device__ __forceinline__ void cp16(uint32_t dst, const void* src) {
    asm volatile("cp.async.cg.shared.global [%0], [%1], 16;"
                 :: "r"(dst), "l"(src));
}
__device__ __forceinline__ void cp_commit() {
    asm volatile("cp.async.commit_group;" ::: "memory");
}
__device__ __forceinline__ void cp_wait0() {
    asm volatile("cp.async.wait_group 0;" ::: "memory");
}

// ------------------------------ k0: decoder att -----------------------------
__global__ void k0_decoder(const float* __restrict__ dec,
                           const float* __restrict__ Wd,
                           const float* __restrict__ bd,
                           const float* __restrict__ be) {
    int b = blockIdx.x, ah = blockIdx.y, t = threadIdx.x;
    __shared__ float ds[512];
    ds[t]       = dec[b * 512 + t];
    ds[t + 256] = dec[b * 512 + t + 256];
    __syncthreads();
    int a = ah * 256 + t;
    float acc = be[a] + bd[a];
#pragma unroll 8
    for (int h = 0; h < 512; h++) acc += ds[h] * Wd[h * 512 + a];
    g_D[b * 512 + a] = acc;
}

// ------------------------------ kW: stage W_enc -----------------------------
__global__ void kW_convert(const float* __restrict__ We) {
    int gid = blockIdx.x * 256 + threadIdx.x;   // 0..524287
    int k = gid >> 9, n = gid & 511;
    float w = We[gid];
    __nv_bfloat16 hi = __float2bfloat16(w);
    float rem = w - __bfloat162float(hi);
    __nv_bfloat16 lo = __float2bfloat16(rem);
    int kc = k >> 6, kl = k & 63, nc = n >> 8, nl = n & 255;
    int piece = nc * 16 + kc;
    uint32_t sw = swz((uint32_t)nl * 128u + (uint32_t)kl * 2u);
    unsigned char* basep = g_Bt + (size_t)piece * 65536;
    *(__nv_bfloat16*)(basep + sw)         = hi;
    *(__nv_bfloat16*)(basep + 32768 + sw) = lo;
}

// ------------------------------ kA: stage enc -------------------------------
__global__ __launch_bounds__(256)
void kA_convert(const float* __restrict__ enc) {
    int base = blockIdx.x * 256 + threadIdx.x;
#pragma unroll
    for (int i = 0; i < 8; i++) {
        int gid = base + i * 2097152;          // 8192 blocks * 256 threads
        int kq = gid & 15;
        int rl = (gid >> 4) & 127;
        int kc = (gid >> 11) & 15;
        int rb = gid >> 15;
        float4 f = ((const float4*)enc)[((size_t)(rb * 128 + rl)) * 256 + kc * 16 + kq];
        __nv_bfloat16 h0 = __float2bfloat16(f.x), h1 = __float2bfloat16(f.y);
        __nv_bfloat16 h2 = __float2bfloat16(f.z), h3 = __float2bfloat16(f.w);
        __nv_bfloat16 l0 = __float2bfloat16(f.x - __bfloat162float(h0));
        __nv_bfloat16 l1 = __float2bfloat16(f.y - __bfloat162float(h1));
        __nv_bfloat16 l2 = __float2bfloat16(f.z - __bfloat162float(h2));
        __nv_bfloat16 l3 = __float2bfloat16(f.w - __bfloat162float(h3));
        __nv_bfloat162 ph0 = __nv_bfloat162(h0, h1), ph1 = __nv_bfloat162(h2, h3);
        __nv_bfloat162 pl0 = __nv_bfloat162(l0, l1), pl1 = __nv_bfloat162(l2, l3);
        unsigned char* basep = g_At + (size_t)(rb * 16 + kc) * 32768;
        uint32_t sw = swz((uint32_t)rl * 128u + (uint32_t)kq * 8u);
        *(uint2*)(basep + sw)         = make_uint2(*(uint32_t*)&ph0, *(uint32_t*)&ph1);
        *(uint2*)(basep + 16384 + sw) = make_uint2(*(uint32_t*)&pl0, *(uint32_t*)&pl1);
    }
}

// ------------------------------ K1: persistent HMMA scores ------------------
#define SA_OFF 0
#define SB_OFF 32768
#define BUFSTRIDE 98304
#define SM_SMEM (2 * BUFSTRIDE)
#define K1_THREADS 512

__global__ __launch_bounds__(K1_THREADS)
void k1_mma(const float* __restrict__ Wa) {
    extern __shared__ char smem[];
    __shared__ float s_sc[128];
    const uint32_t sb = smem_u32(smem);
    const int tid = threadIdx.x;
    const int wid = tid >> 5, lid = tid & 31;
    const int wm = wid & 3;            // m group: rows wm*32..+32
    const int wn = wid >> 2;           // n group: cols wn*64..+64
    const int r4 = lid >> 2, q = lid & 3;

    const uint32_t aoffb = (uint32_t)(wm * 32 + (lid & 15)) * 128u + ((lid >> 4) * 16u);
    const uint32_t boffb = (uint32_t)(wn * 64 + (lid & 7) + ((lid >> 4) << 3)) * 128u +
                           (((lid >> 3) & 1) * 16u);

    // (tile, nc) units strided over CTAs: unit u = bid + j*K1_GRID
    const int nunits = (NUNITS - blockIdx.x + K1_GRID - 1) / K1_GRID;
    const int nsteps = nunits * 16;

    auto stage = [&](int s, int bufsel) {
        int u  = blockIdx.x + (s >> 4) * K1_GRID;
        int tile = u >> 1, ncs = u & 1;
        int kc = s & 15;
        const unsigned char* srcA = g_At + (size_t)(tile * 16 + kc) * 32768;
        uint32_t dstA = sb + bufsel * BUFSTRIDE + SA_OFF;
#pragma unroll
        for (int v = 0; v < 4; v++)
            cp16(dstA + (v * K1_THREADS + tid) * 16,
                 srcA + (size_t)(v * K1_THREADS + tid) * 16);
        const unsigned char* srcB = g_Bt + (size_t)(ncs * 16 + kc) * 65536;
        uint32_t dstB = sb + bufsel * BUFSTRIDE + SB_OFF;
#pragma unroll
        for (int v = 0; v < 8; v++)
            cp16(dstB + (v * K1_THREADS + tid) * 16,
                 srcB + (size_t)(v * K1_THREADS + tid) * 16);
        cp_commit();
    };

    float acc[2][8][4];
#pragma unroll
    for (int mt = 0; mt < 2; mt++)
#pragma unroll
        for (int nt = 0; nt < 8; nt++)
#pragma unroll
            for (int v = 0; v < 4; v++) acc[mt][nt][v] = 0.f;

    stage(0, 0);
    cp_wait0();
    __syncthreads();

    for (int s = 0; s < nsteps; s++) {
        const int cur = s & 1;
        const int u  = blockIdx.x + (s >> 4) * K1_GRID;
        const int tile = u >> 1, ncs = u & 1;
        const int kc = s & 15;
        const uint32_t aB = sb + cur * BUFSTRIDE + SA_OFF;
        const uint32_t bB = sb + cur * BUFSTRIDE + SB_OFF;

        if (s + 1 < nsteps) stage(s + 1, cur ^ 1);   // overlaps MMA below

#pragma unroll
        for (int kk = 0; kk < 4; kk++) {
            uint32_t ah[2][4], al[2][4];
#pragma unroll
            for (int mt = 0; mt < 2; mt++) {
                uint32_t off = aoffb + (uint32_t)(mt * 16) * 128u + kk * 32u;
                ldsm4(ah[mt], aB + swz(off));
                ldsm4(al[mt], aB + 16384 + swz(off));
            }
#pragma unroll
            for (int ntp = 0; ntp < 4; ntp++) {
                uint32_t off = boffb + (uint32_t)(ntp * 16) * 128u + kk * 32u;
                uint32_t bh[4], bl[4];
                ldsm4(bh, bB + swz(off));
                ldsm4(bl, bB + 32768 + swz(off));
#pragma unroll
                for (int mt = 0; mt < 2; mt++) {
                    mma_bf16(acc[mt][2 * ntp],     ah[mt], bh[0], bh[1]);
                    mma_bf16(acc[mt][2 * ntp],     al[mt], bh[0], bh[1]);
                    mma_bf16(acc[mt][2 * ntp],     ah[mt], bl[0], bl[1]);
                    mma_bf16(acc[mt][2 * ntp + 1], ah[mt], bh[2], bh[3]);
                    mma_bf16(acc[mt][2 * ntp + 1], al[mt], bh[2], bh[3]);
                    mma_bf16(acc[mt][2 * ntp + 1], ah[mt], bl[2], bl[3]);
                }
            }
        }

        if (kc == 15) {
            // unit epilogue: partial score for (tile, ncs); overlaps s+1 copies
            const int r0 = tile * 128;
            const int b  = r0 >> 11;
            if (tid < 128) s_sc[tid] = 0.f;
            __syncthreads();
#pragma unroll
            for (int mt = 0; mt < 2; mt++) {
                float p0 = 0.f, p1 = 0.f;
#pragma unroll
                for (int nt = 0; nt < 8; nt++) {
                    int c0 = ncs * 256 + wn * 64 + nt * 8 + q * 2;
                    float d0v = g_D[b * 512 + c0], d1v = g_D[b * 512 + c0 + 1];
                    float w0 = Wa[c0], w1 = Wa[c0 + 1];
                    p0 += tanhf(acc[mt][nt][0] + d0v) * w0 + tanhf(acc[mt][nt][1] + d1v) * w1;
                    p1 += tanhf(acc[mt][nt][2] + d0v) * w0 + tanhf(acc[mt][nt][3] + d1v) * w1;
                }
                p0 += __shfl_xor_sync(0xffffffffu, p0, 1);
                p0 += __shfl_xor_sync(0xffffffffu, p0, 2);
                p1 += __shfl_xor_sync(0xffffffffu, p1, 1);
                p1 += __shfl_xor_sync(0xffffffffu, p1, 2);
                if (q == 0) {
                    atomicAdd(&s_sc[wm * 32 + mt * 16 + r4], p0);
                    atomicAdd(&s_sc[wm * 32 + mt * 16 + r4 + 8], p1);
                }
            }
            __syncthreads();
            if (tid < 128) g_sc2[ncs][r0 + tid] = s_sc[tid];
            // zero accumulators for next unit
#pragma unroll
            for (int mt = 0; mt < 2; mt++)
#pragma unroll
                for (int nt = 0; nt < 8; nt++)
#pragma unroll
                    for (int v = 0; v < 4; v++) acc[mt][nt][v] = 0.f;
        }

        cp_wait0();
        __syncthreads();
    }
}

// ------------------------------ k2a: softmax (+mask detect) -----------------
__global__ void k2a_softmax(const unsigned char* __restrict__ masks) {
    int b = blockIdx.x, t = threadIdx.x;
    __shared__ float sm[2048];
    __shared__ float red[256];
    const float NEG_INF = __int_as_float(0xff800000);

    int found = 0;
    for (int j = t; j < 16384; j += 256)
        if (masks[4 * j + 1]) found = 1;
    const int mode = __syncthreads_or(found);   // 1 = byte elems, 0 = 4-byte
    const unsigned int* m32 = (const unsigned int*)masks;

    float lmax = NEG_INF;
#pragma unroll
    for (int v = 0; v < 8; v++) {
        int idx = v * 256 + t;
        float sc = g_sc2[0][b * 2048 + idx] + g_sc2[1][b * 2048 + idx];
        bool masked = mode ? (masks[b * 2048 + idx] != 0) : (m32[b * 2048 + idx] != 0u);
        if (masked) sc = NEG_INF;
        sm[idx] = sc;
        lmax = fmaxf(lmax, sc);
    }
    red[t] = lmax;
    __syncthreads();
    for (int o = 128; o > 0; o >>= 1) {
        if (t < o) red[t] = fmaxf(red[t], red[t + o]);
        __syncthreads();
    }
    float bmax = red[0];
    __syncthreads();

    float lsum = 0.f;
#pragma unroll
    for (int v = 0; v < 8; v++) {
        int idx = v * 256 + t;
        float e = expf(sm[idx] - bmax);
        sm[idx] = e;
        lsum += e;
    }
    red[t] = lsum;
    __syncthreads();
    for (int o = 128; o > 0; o >>= 1) {
        if (t < o) red[t] += red[t + o];
        __syncthreads();
    }
    float inv = 1.f / red[0];
#pragma unroll
    for (int v = 0; v < 8; v++) {
        int idx = v * 256 + t;
        g_weights[b * 2048 + idx] = sm[idx] * inv;
    }
}

// ------------------------------ k2b: weighted sum ---------------------------
__global__ void k2b_partial(const float* __restrict__ enc) {
    int ch = blockIdx.x, b = blockIdx.y, t = threadIdx.x;
    __shared__ float w[128];
    if (t < 128) w[t] = g_weights[b * 2048 + ch * 128 + t];
    __syncthreads();

    const float4* rowbase =
        reinterpret_cast<const float4*>(enc) + (size_t)(b * 2048 + ch * 128) * 256;
    float4 acc = make_float4(0.f, 0.f, 0.f, 0.f);
    for (int si = 0; si < 128; si++) {
        float wv = w[si];
        if (wv != 0.f) {
            float4 v = rowbase[(size_t)si * 256 + t];
            acc.x += wv * v.x; acc.y += wv * v.y;
            acc.z += wv * v.z; acc.w += wv * v.w;
        }
    }
    reinterpret_cast<float4*>(g_partial)[(b * NCHUNK + ch) * 256 + t] = acc;
}

// ------------------------------ k2c: final GEMV -----------------------------
__global__ void k2c_context(const float* __restrict__ We,
                            const float* __restrict__ be,
                            float* __restrict__ out) {
    int b = blockIdx.x, t = threadIdx.x;
    __shared__ float ctx[1024];
    float4 s = make_float4(0.f, 0.f, 0.f, 0.f);
#pragma unroll
    for (int chn = 0; chn < NCHUNK; chn++) {
        float4 v = reinterpret_cast<const float4*>(g_partial)[(b * NCHUNK + chn) * 256 + t];
        s.x += v.x; s.y += v.y; s.z += v.z; s.w += v.w;
    }
    reinterpret_cast<float4*>(ctx)[t] = s;
    __syncthreads();

    float acc0 = be[t], acc1 = be[t + 256];
#pragma unroll 4
    for (int k = 0; k < 1024; k++) {
        float c = ctx[k];
        const float* wr = We + k * 512;
        acc0 += c * wr[t];
        acc1 += c * wr[t + 256];
    }
    out[b * 512 + t]       = acc0;
    out[b * 512 + t + 256] = acc1;
}

// ---------------------------------------------------------------------------
extern "C" void kernel_launch(void* const* d_in, const int* in_sizes, int n_in,
                              void* d_out, int out_size) {
    const float*         enc   = (const float*)d_in[0];
    const float*         dec   = (const float*)d_in[1];
    const unsigned char* masks = (const unsigned char*)d_in[2];
    const float*         We    = (const float*)d_in[3];
    const float*         be    = (const float*)d_in[4];
    const float*         Wd    = (const float*)d_in[5];
    const float*         bd    = (const float*)d_in[6];
    const float*         Wa    = (const float*)d_in[7];
    float* out = (float*)d_out;

    static int configured = 0;
    if (!configured) {
        cudaFuncSetAttribute(k1_mma, cudaFuncAttributeMaxDynamicSharedMemorySize, SM_SMEM);
        configured = 1;
    }

    dim3 g0(Bn, 2);
    k0_decoder<<<g0, 256>>>(dec, Wd, bd, be);
    kW_convert<<<2048, 256>>>(We);
    kA_convert<<<8192, 256>>>(enc);
    k1_mma<<<K1_GRID, K1_THREADS, SM_SMEM>>>(Wa);
    k2a_softmax<<<Bn, 256>>>(masks);
    dim3 g2b(NCHUNK, Bn);
    k2b_partial<<<g2b, 256>>>(enc);
    k2c_context<<<Bn, 256>>>(We, be, out);
}

// round 12
// speedup vs baseline: 1.2118x; 1.0206x over previous
#include <cuda_runtime.h>
#include <cuda_bf16.h>
#include <math.h>
#include <stdint.h>

#define Bn 32
#define Sn 2048
#define NCHUNK 16
#define NTILES 512           // 128-row tiles
#define NUNITS 1024          // (tile, nc) units
#define K1_GRID 148

// ------------------------------ device scratch ------------------------------
__device__ float g_D[Bn * 512];
__device__ float g_sc2[2][Bn * Sn];     // per-nc score partials
__device__ float g_weights[Bn * Sn];
__device__ float g_partial[Bn * NCHUNK * 1024];
// W_enc staged as bf16 hi/lo, SW128-swizzled [n][k] tiles.
__device__ __align__(16) unsigned char g_Bt[32 * 65536];
// enc staged as bf16 hi/lo, swizzled smem-image pieces.
__device__ __align__(16) unsigned char g_At[512 * 16 * 32768ull];

// ------------------------------ helpers -------------------------------------
__device__ __forceinline__ uint32_t smem_u32(const void* p) {
    uint32_t a;
    asm("{ .reg .u64 t; cvta.to.shared.u64 t, %1; cvt.u32.u64 %0, t; }"
        : "=r"(a) : "l"(p));
    return a;
}
__device__ __forceinline__ uint32_t swz(uint32_t off) {
    return off ^ ((off >> 3) & 0x70);
}
__device__ __forceinline__ void ldsm4(uint32_t* r, uint32_t addr) {
    asm volatile("ldmatrix.sync.aligned.m8n8.x4.shared.b16 {%0,%1,%2,%3}, [%4];"
                 : "=r"(r[0]), "=r"(r[1]), "=r"(r[2]), "=r"(r[3]) : "r"(addr));
}
__device__ __forceinline__ void mma_bf16(float* c, const uint32_t* a,
                                         uint32_t b0, uint32_t b1) {
    asm("mma.sync.aligned.m16n8k16.row.col.f32.bf16.bf16.f32 "
        "{%0,%1,%2,%3},{%4,%5,%6,%7},{%8,%9},{%0,%1,%2,%3};"
        : "+f"(c[0]), "+f"(c[1]), "+f"(c[2]), "+f"(c[3])
        : "r"(a[0]), "r"(a[1]), "r"(a[2]), "r"(a[3]), "r"(b0), "r"(b1));
}
__device__ __forceinline__ void cp16(uint32_t dst, const void* src) {
    asm volatile("cp.async.cg.shared.global [%0], [%1], 16;"
                 :: "r"(dst), "l"(src));
}
__device__ __forceinline__ void cp_commit() {
    asm volatile("cp.async.commit_group;" ::: "memory");
}
__device__ __forceinline__ void cp_wait0() {
    asm volatile("cp.async.wait_group 0;" ::: "memory");
}

// ------------------------------ k_prep: kA + kW + k0 fused ------------------
// blocks [0,8192): enc conversion; [8192,10240): W_enc staging; [10240,10304): decoder att
__global__ __launch_bounds__(256)
void k_prep(const float* __restrict__ enc, const float* __restrict__ We,
            const float* __restrict__ dec, const float* __restrict__ Wd,
            const float* __restrict__ bd, const float* __restrict__ be) {
    __shared__ float ds[512];
    const int bi = blockIdx.x, tid = threadIdx.x;

    if (bi < 8192) {
        // ---- kA: enc -> bf16 hi/lo swizzled pieces ----
        int base = bi * 256 + tid;
#pragma unroll
        for (int i = 0; i < 8; i++) {
            int gid = base + i * 2097152;
            int kq = gid & 15;
            int rl = (gid >> 4) & 127;
            int kc = (gid >> 11) & 15;
            int rb = gid >> 15;
            float4 f = ((const float4*)enc)[((size_t)(rb * 128 + rl)) * 256 + kc * 16 + kq];
            __nv_bfloat16 h0 = __float2bfloat16(f.x), h1 = __float2bfloat16(f.y);
            __nv_bfloat16 h2 = __float2bfloat16(f.z), h3 = __float2bfloat16(f.w);
            __nv_bfloat16 l0 = __float2bfloat16(f.x - __bfloat162float(h0));
            __nv_bfloat16 l1 = __float2bfloat16(f.y - __bfloat162float(h1));
            __nv_bfloat16 l2 = __float2bfloat16(f.z - __bfloat162float(h2));
            __nv_bfloat16 l3 = __float2bfloat16(f.w - __bfloat162float(h3));
            __nv_bfloat162 ph0 = __nv_bfloat162(h0, h1), ph1 = __nv_bfloat162(h2, h3);
            __nv_bfloat162 pl0 = __nv_bfloat162(l0, l1), pl1 = __nv_bfloat162(l2, l3);
            unsigned char* basep = g_At + (size_t)(rb * 16 + kc) * 32768;
            uint32_t sw = swz((uint32_t)rl * 128u + (uint32_t)kq * 8u);
            *(uint2*)(basep + sw)         = make_uint2(*(uint32_t*)&ph0, *(uint32_t*)&ph1);
            *(uint2*)(basep + 16384 + sw) = make_uint2(*(uint32_t*)&pl0, *(uint32_t*)&pl1);
        }
    } else if (bi < 10240) {
        // ---- kW: W_enc -> bf16 hi/lo swizzled tiles ----
        int gid = (bi - 8192) * 256 + tid;
        int k = gid >> 9, n = gid & 511;
        float w = We[gid];
        __nv_bfloat16 hi = __float2bfloat16(w);
        float rem = w - __bfloat162float(hi);
        __nv_bfloat16 lo = __float2bfloat16(rem);
        int kc = k >> 6, kl = k & 63, nc = n >> 8, nl = n & 255;
        int piece = nc * 16 + kc;
        uint32_t sw = swz((uint32_t)nl * 128u + (uint32_t)kl * 2u);
        unsigned char* basep = g_Bt + (size_t)piece * 65536;
        *(__nv_bfloat16*)(basep + sw)         = hi;
        *(__nv_bfloat16*)(basep + 32768 + sw) = lo;
    } else {
        // ---- k0: decoder attention row ----
        int idx = bi - 10240;           // 0..63
        int b = idx >> 1, ah = idx & 1;
        ds[tid]       = dec[b * 512 + tid];
        ds[tid + 256] = dec[b * 512 + tid + 256];
        __syncthreads();
        int a = ah * 256 + tid;
        float acc = be[a] + bd[a];
#pragma unroll 8
        for (int h = 0; h < 512; h++) acc += ds[h] * Wd[h * 512 + a];
        g_D[b * 512 + a] = acc;
    }
}

// ------------------------------ K1: persistent HMMA scores ------------------
#define SA_OFF 0
#define SB_OFF 32768
#define BUFSTRIDE 98304
#define SM_SMEM (2 * BUFSTRIDE)
#define K1_THREADS 512

__global__ __launch_bounds__(K1_THREADS)
void k1_mma(const float* __restrict__ Wa) {
    extern __shared__ char smem[];
    __shared__ float s_sc[128];
    const uint32_t sb = smem_u32(smem);
    const int tid = threadIdx.x;
    const int wid = tid >> 5, lid = tid & 31;
    const int wm = wid & 3;
    const int wn = wid >> 2;
    const int r4 = lid >> 2, q = lid & 3;

    const uint32_t aoffb = (uint32_t)(wm * 32 + (lid & 15)) * 128u + ((lid >> 4) * 16u);
    const uint32_t boffb = (uint32_t)(wn * 64 + (lid & 7) + ((lid >> 4) << 3)) * 128u +
                           (((lid >> 3) & 1) * 16u);

    const int nunits = (NUNITS - blockIdx.x + K1_GRID - 1) / K1_GRID;
    const int nsteps = nunits * 16;

    auto stage = [&](int s, int bufsel) {
        int u  = blockIdx.x + (s >> 4) * K1_GRID;
        int tile = u >> 1, ncs = u & 1;
        int kc = s & 15;
        const unsigned char* srcA = g_At + (size_t)(tile * 16 + kc) * 32768;
        uint32_t dstA = sb + bufsel * BUFSTRIDE + SA_OFF;
#pragma unroll
        for (int v = 0; v < 4; v++)
            cp16(dstA + (v * K1_THREADS + tid) * 16,
                 srcA + (size_t)(v * K1_THREADS + tid) * 16);
        const unsigned char* srcB = g_Bt + (size_t)(ncs * 16 + kc) * 65536;
        uint32_t dstB = sb + bufsel * BUFSTRIDE + SB_OFF;
#pragma unroll
        for (int v = 0; v < 8; v++)
            cp16(dstB + (v * K1_THREADS + tid) * 16,
                 srcB + (size_t)(v * K1_THREADS + tid) * 16);
        cp_commit();
    };

    float acc[2][8][4];
#pragma unroll
    for (int mt = 0; mt < 2; mt++)
#pragma unroll
        for (int nt = 0; nt < 8; nt++)
#pragma unroll
            for (int v = 0; v < 4; v++) acc[mt][nt][v] = 0.f;

    stage(0, 0);
    cp_wait0();
    __syncthreads();

    for (int s = 0; s < nsteps; s++) {
        const int cur = s & 1;
        const int u  = blockIdx.x + (s >> 4) * K1_GRID;
        const int tile = u >> 1, ncs = u & 1;
        const int kc = s & 15;
        const uint32_t aB = sb + cur * BUFSTRIDE + SA_OFF;
        const uint32_t bB = sb + cur * BUFSTRIDE + SB_OFF;

        if (s + 1 < nsteps) stage(s + 1, cur ^ 1);

#pragma unroll
        for (int kk = 0; kk < 4; kk++) {
            uint32_t ah[2][4], al[2][4];
#pragma unroll
            for (int mt = 0; mt < 2; mt++) {
                uint32_t off = aoffb + (uint32_t)(mt * 16) * 128u + kk * 32u;
                ldsm4(ah[mt], aB + swz(off));
                ldsm4(al[mt], aB + 16384 + swz(off));
            }
#pragma unroll
            for (int ntp = 0; ntp < 4; ntp++) {
                uint32_t off = boffb + (uint32_t)(ntp * 16) * 128u + kk * 32u;
                uint32_t bh[4], bl[4];
                ldsm4(bh, bB + swz(off));
                ldsm4(bl, bB + 32768 + swz(off));
#pragma unroll
                for (int mt = 0; mt < 2; mt++) {
                    mma_bf16(acc[mt][2 * ntp],     ah[mt], bh[0], bh[1]);
                    mma_bf16(acc[mt][2 * ntp],     al[mt], bh[0], bh[1]);
                    mma_bf16(acc[mt][2 * ntp],     ah[mt], bl[0], bl[1]);
                    mma_bf16(acc[mt][2 * ntp + 1], ah[mt], bh[2], bh[3]);
                    mma_bf16(acc[mt][2 * ntp + 1], al[mt], bh[2], bh[3]);
                    mma_bf16(acc[mt][2 * ntp + 1], ah[mt], bl[2], bl[3]);
                }
            }
        }

        if (kc == 15) {
            const int r0 = tile * 128;
            const int b  = r0 >> 11;
            if (tid < 128) s_sc[tid] = 0.f;
            __syncthreads();
#pragma unroll
            for (int mt = 0; mt < 2; mt++) {
                float p0 = 0.f, p1 = 0.f;
#pragma unroll
                for (int nt = 0; nt < 8; nt++) {
                    int c0 = ncs * 256 + wn * 64 + nt * 8 + q * 2;
                    float d0v = g_D[b * 512 + c0], d1v = g_D[b * 512 + c0 + 1];
                    float w0 = Wa[c0], w1 = Wa[c0 + 1];
                    p0 += tanhf(acc[mt][nt][0] + d0v) * w0 + tanhf(acc[mt][nt][1] + d1v) * w1;
                    p1 += tanhf(acc[mt][nt][2] + d0v) * w0 + tanhf(acc[mt][nt][3] + d1v) * w1;
                }
                p0 += __shfl_xor_sync(0xffffffffu, p0, 1);
                p0 += __shfl_xor_sync(0xffffffffu, p0, 2);
                p1 += __shfl_xor_sync(0xffffffffu, p1, 1);
                p1 += __shfl_xor_sync(0xffffffffu, p1, 2);
                if (q == 0) {
                    atomicAdd(&s_sc[wm * 32 + mt * 16 + r4], p0);
                    atomicAdd(&s_sc[wm * 32 + mt * 16 + r4 + 8], p1);
                }
            }
            __syncthreads();
            if (tid < 128) g_sc2[ncs][r0 + tid] = s_sc[tid];
#pragma unroll
            for (int mt = 0; mt < 2; mt++)
#pragma unroll
                for (int nt = 0; nt < 8; nt++)
#pragma unroll
                    for (int v = 0; v < 4; v++) acc[mt][nt][v] = 0.f;
        }

        cp_wait0();
        __syncthreads();
    }
}

// ------------------------------ k2a: softmax (+mask detect) -----------------
__global__ void k2a_softmax(const unsigned char* __restrict__ masks) {
    int b = blockIdx.x, t = threadIdx.x;
    __shared__ float sm[2048];
    __shared__ float red[256];
    const float NEG_INF = __int_as_float(0xff800000);

    int found = 0;
    for (int j = t; j < 16384; j += 256)
        if (masks[4 * j + 1]) found = 1;
    const int mode = __syncthreads_or(found);   // 1 = byte elems, 0 = 4-byte
    const unsigned int* m32 = (const unsigned int*)masks;

    float lmax = NEG_INF;
#pragma unroll
    for (int v = 0; v < 8; v++) {
        int idx = v * 256 + t;
        float sc = g_sc2[0][b * 2048 + idx] + g_sc2[1][b * 2048 + idx];
        bool masked = mode ? (masks[b * 2048 + idx] != 0) : (m32[b * 2048 + idx] != 0u);
        if (masked) sc = NEG_INF;
        sm[idx] = sc;
        lmax = fmaxf(lmax, sc);
    }
    red[t] = lmax;
    __syncthreads();
    for (int o = 128; o > 0; o >>= 1) {
        if (t < o) red[t] = fmaxf(red[t], red[t + o]);
        __syncthreads();
    }
    float bmax = red[0];
    __syncthreads();

    float lsum = 0.f;
#pragma unroll
    for (int v = 0; v < 8; v++) {
        int idx = v * 256 + t;
        float e = expf(sm[idx] - bmax);
        sm[idx] = e;
        lsum += e;
    }
    red[t] = lsum;
    __syncthreads();
    for (int o = 128; o > 0; o >>= 1) {
        if (t < o) red[t] += red[t + o];
        __syncthreads();
    }
    float inv = 1.f / red[0];
#pragma unroll
    for (int v = 0; v < 8; v++) {
        int idx = v * 256 + t;
        g_weights[b * 2048 + idx] = sm[idx] * inv;
    }
}

// ------------------------------ k2b: compacted weighted sum -----------------
__global__ void k2b_partial(const float* __restrict__ enc) {
    int ch = blockIdx.x, b = blockIdx.y, t = threadIdx.x;
    __shared__ float wv[132];
    __shared__ int   sidx[132];
    __shared__ int   wcnt[4];

    float myw = 0.f;
    int pred = 0;
    if (t < 128) {
        myw = g_weights[b * 2048 + ch * 128 + t];
        pred = (myw != 0.f) ? 1 : 0;
    }
    unsigned bal = __ballot_sync(0xffffffffu, pred);
    if (t < 128 && (t & 31) == 0) wcnt[t >> 5] = __popc(bal);
    __syncthreads();
    int c0 = wcnt[0], c1 = wcnt[1], c2 = wcnt[2], c3 = wcnt[3];
    int cnt = c0 + c1 + c2 + c3;
    int cnt4 = (cnt + 3) & ~3;
    if (t < 128 && pred) {
        int w = t >> 5;
        int off = (w > 0 ? c0 : 0) + (w > 1 ? c1 : 0) + (w > 2 ? c2 : 0);
        off += __popc(bal & ((1u << (t & 31)) - 1u));
        sidx[off] = t;
        wv[off] = myw;
    }
    if (t < cnt4 - cnt) { sidx[cnt + t] = 0; wv[cnt + t] = 0.f; }
    __syncthreads();

    const float4* rowbase =
        reinterpret_cast<const float4*>(enc) + (size_t)(b * 2048 + ch * 128) * 256;
    float4 acc = make_float4(0.f, 0.f, 0.f, 0.f);
    for (int i = 0; i < cnt4; i += 4) {
        int i0 = sidx[i], i1 = sidx[i + 1], i2 = sidx[i + 2], i3 = sidx[i + 3];
        float w0 = wv[i], w1 = wv[i + 1], w2 = wv[i + 2], w3 = wv[i + 3];
        float4 v0 = rowbase[(size_t)i0 * 256 + t];
        float4 v1 = rowbase[(size_t)i1 * 256 + t];
        float4 v2 = rowbase[(size_t)i2 * 256 + t];
        float4 v3 = rowbase[(size_t)i3 * 256 + t];
        acc.x += w0 * v0.x + w1 * v1.x + w2 * v2.x + w3 * v3.x;
        acc.y += w0 * v0.y + w1 * v1.y + w2 * v2.y + w3 * v3.y;
        acc.z += w0 * v0.z + w1 * v1.z + w2 * v2.z + w3 * v3.z;
        acc.w += w0 * v0.w + w1 * v1.w + w2 * v2.w + w3 * v3.w;
    }
    reinterpret_cast<float4*>(g_partial)[(b * NCHUNK + ch) * 256 + t] = acc;
}

// ------------------------------ k2c: final GEMV -----------------------------
__global__ void k2c_context(const float* __restrict__ We,
                            const float* __restrict__ be,
                            float* __restrict__ out) {
    int b = blockIdx.x, t = threadIdx.x;
    __shared__ float ctx[1024];
    float4 s = make_float4(0.f, 0.f, 0.f, 0.f);
#pragma unroll
    for (int chn = 0; chn < NCHUNK; chn++) {
        float4 v = reinterpret_cast<const float4*>(g_partial)[(b * NCHUNK + chn) * 256 + t];
        s.x += v.x; s.y += v.y; s.z += v.z; s.w += v.w;
    }
    reinterpret_cast<float4*>(ctx)[t] = s;
    __syncthreads();

    float acc0 = be[t], acc1 = be[t + 256];
#pragma unroll 4
    for (int k = 0; k < 1024; k++) {
        float c = ctx[k];
        const float* wr = We + k * 512;
        acc0 += c * wr[t];
        acc1 += c * wr[t + 256];
    }
    out[b * 512 + t]       = acc0;
    out[b * 512 + t + 256] = acc1;
}

// ---------------------------------------------------------------------------
extern "C" void kernel_launch(void* const* d_in, const int* in_sizes, int n_in,
                              void* d_out, int out_size) {
    const float*         enc   = (const float*)d_in[0];
    const float*         dec   = (const float*)d_in[1];
    const unsigned char* masks = (const unsigned char*)d_in[2];
    const float*         We    = (const float*)d_in[3];
    const float*         be    = (const float*)d_in[4];
    const float*         Wd    = (const float*)d_in[5];
    const float*         bd    = (const float*)d_in[6];
    const float*         Wa    = (const float*)d_in[7];
    float* out = (float*)d_out;

    static int configured = 0;
    if (!configured) {
        cudaFuncSetAttribute(k1_mma, cudaFuncAttributeMaxDynamicSharedMemorySize, SM_SMEM);
        configured = 1;
    }

    k_prep<<<10304, 256>>>(enc, We, dec, Wd, bd, be);
    k1_mma<<<K1_GRID, K1_THREADS, SM_SMEM>>>(Wa);
    k2a_softmax<<<Bn, 256>>>(masks);
    dim3 g2b(NCHUNK, Bn);
    k2b_partial<<<g2b, 256>>>(enc);
    k2c_context<<<Bn, 256>>>(We, be, out);
}

// round 13
// speedup vs baseline: 1.5169x; 1.2518x over previous
#include <cuda_runtime.h>
#include <cuda_fp16.h>
#include <math.h>
#include <stdint.h>

#define Bn 32
#define Sn 2048
#define NCHUNK 16
#define NTILES 512           // 128-row tiles
#define NUNITS 1024          // (tile, nc) units
#define K1_GRID 148

// ------------------------------ device scratch ------------------------------
__device__ float g_D[Bn * 512];
__device__ float g_sc2[2][Bn * Sn];     // per-nc score partials
__device__ float g_weights[Bn * Sn];
__device__ float g_partial[Bn * NCHUNK * 1024];
// W_enc staged as fp16, SW128-swizzled [n][k] tiles.
// 32 pieces (nc 0..1 x kc 0..15), each 32KB
__device__ __align__(16) unsigned char g_Bt[32 * 32768];
// enc staged as fp16 hi/lo, swizzled smem-image pieces.
// piece p = rowblock*16 + kc (rowblock 0..511): 32KB = [hi 16KB][lo 16KB]
__device__ __align__(16) unsigned char g_At[512 * 16 * 32768ull];

// ------------------------------ helpers -------------------------------------
__device__ __forceinline__ uint32_t smem_u32(const void* p) {
    uint32_t a;
    asm("{ .reg .u64 t; cvta.to.shared.u64 t, %1; cvt.u32.u64 %0, t; }"
        : "=r"(a) : "l"(p));
    return a;
}
__device__ __forceinline__ uint32_t swz(uint32_t off) {
    return off ^ ((off >> 3) & 0x70);
}
__device__ __forceinline__ void ldsm4(uint32_t* r, uint32_t addr) {
    asm volatile("ldmatrix.sync.aligned.m8n8.x4.shared.b16 {%0,%1,%2,%3}, [%4];"
                 : "=r"(r[0]), "=r"(r[1]), "=r"(r[2]), "=r"(r[3]) : "r"(addr));
}
__device__ __forceinline__ void mma_f16(float* c, const uint32_t* a,
                                        uint32_t b0, uint32_t b1) {
    asm("mma.sync.aligned.m16n8k16.row.col.f32.f16.f16.f32 "
        "{%0,%1,%2,%3},{%4,%5,%6,%7},{%8,%9},{%0,%1,%2,%3};"
        : "+f"(c[0]), "+f"(c[1]), "+f"(c[2]), "+f"(c[3])
        : "r"(a[0]), "r"(a[1]), "r"(a[2]), "r"(a[3]), "r"(b0), "r"(b1));
}
__device__ __forceinline__ void cp16(uint32_t dst, const void* src) {
    asm volatile("cp.async.cg.shared.global [%0], [%1], 16;"
                 :: "r"(dst), "l"(src));
}
__device__ __forceinline__ void cp_commit() {
    asm volatile("cp.async.commit_group;" ::: "memory");
}
__device__ __forceinline__ void cp_wait0() {
    asm volatile("cp.async.wait_group 0;" ::: "memory");
}
__device__ __forceinline__ uint32_t pack_half2(__half a, __half b) {
    __half2 h = __halves2half2(a, b);
    return *(uint32_t*)&h;
}

// ------------------------------ k_prep: kA + kW + k0 fused ------------------
// blocks [0,8192): enc conversion; [8192,10240): W_enc staging; [10240,10304): decoder att
__global__ __launch_bounds__(256)
void k_prep(const float* __restrict__ enc, const float* __restrict__ We,
            const float* __restrict__ dec, const float* __restrict__ Wd,
            const float* __restrict__ bd, const float* __restrict__ be) {
    __shared__ float ds[512];
    const int bi = blockIdx.x, tid = threadIdx.x;

    if (bi < 8192) {
        // ---- kA: enc -> fp16 hi/lo swizzled pieces ----
        int base = bi * 256 + tid;
#pragma unroll
        for (int i = 0; i < 8; i++) {
            int gid = base + i * 2097152;
            int kq = gid & 15;
            int rl = (gid >> 4) & 127;
            int kc = (gid >> 11) & 15;
            int rb = gid >> 15;
            float4 f = ((const float4*)enc)[((size_t)(rb * 128 + rl)) * 256 + kc * 16 + kq];
            __half h0 = __float2half_rn(f.x), h1 = __float2half_rn(f.y);
            __half h2 = __float2half_rn(f.z), h3 = __float2half_rn(f.w);
            __half l0 = __float2half_rn(f.x - __half2float(h0));
            __half l1 = __float2half_rn(f.y - __half2float(h1));
            __half l2 = __float2half_rn(f.z - __half2float(h2));
            __half l3 = __float2half_rn(f.w - __half2float(h3));
            unsigned char* basep = g_At + (size_t)(rb * 16 + kc) * 32768;
            uint32_t sw = swz((uint32_t)rl * 128u + (uint32_t)kq * 8u);
            *(uint2*)(basep + sw)         = make_uint2(pack_half2(h0, h1), pack_half2(h2, h3));
            *(uint2*)(basep + 16384 + sw) = make_uint2(pack_half2(l0, l1), pack_half2(l2, l3));
        }
    } else if (bi < 10240) {
        // ---- kW: W_enc -> fp16 swizzled tiles ----
        int gid = (bi - 8192) * 256 + tid;
        int k = gid >> 9, n = gid & 511;
        float w = We[gid];
        __half hw = __float2half_rn(w);
        int kc = k >> 6, kl = k & 63, nc = n >> 8, nl = n & 255;
        int piece = nc * 16 + kc;
        uint32_t sw = swz((uint32_t)nl * 128u + (uint32_t)kl * 2u);
        *(__half*)(g_Bt + (size_t)piece * 32768 + sw) = hw;
    } else {
        // ---- k0: decoder attention row ----
        int idx = bi - 10240;           // 0..63
        int b = idx >> 1, ah = idx & 1;
        ds[tid]       = dec[b * 512 + tid];
        ds[tid + 256] = dec[b * 512 + tid + 256];
        __syncthreads();
        int a = ah * 256 + tid;
        float acc = be[a] + bd[a];
#pragma unroll 8
        for (int h = 0; h < 512; h++) acc += ds[h] * Wd[h * 512 + a];
        g_D[b * 512 + a] = acc;
    }
}

// ------------------------------ K1: persistent HMMA scores ------------------
#define SA_OFF 0
#define SB_OFF 32768
#define BUFSTRIDE 65536
#define SM_SMEM (2 * BUFSTRIDE)
#define K1_THREADS 512

__global__ __launch_bounds__(K1_THREADS)
void k1_mma(const float* __restrict__ Wa) {
    extern __shared__ char smem[];
    __shared__ float s_sc[128];
    const uint32_t sb = smem_u32(smem);
    const int tid = threadIdx.x;
    const int wid = tid >> 5, lid = tid & 31;
    const int wm = wid & 3;
    const int wn = wid >> 2;
    const int r4 = lid >> 2, q = lid & 3;

    const uint32_t aoffb = (uint32_t)(wm * 32 + (lid & 15)) * 128u + ((lid >> 4) * 16u);
    const uint32_t boffb = (uint32_t)(wn * 64 + (lid & 7) + ((lid >> 4) << 3)) * 128u +
                           (((lid >> 3) & 1) * 16u);

    const int nunits = (NUNITS - blockIdx.x + K1_GRID - 1) / K1_GRID;
    const int nsteps = nunits * 16;

    auto stage = [&](int s, int bufsel) {
        int u  = blockIdx.x + (s >> 4) * K1_GRID;
        int tile = u >> 1, ncs = u & 1;
        int kc = s & 15;
        const unsigned char* srcA = g_At + (size_t)(tile * 16 + kc) * 32768;
        uint32_t dstA = sb + bufsel * BUFSTRIDE + SA_OFF;
#pragma unroll
        for (int v = 0; v < 4; v++)
            cp16(dstA + (v * K1_THREADS + tid) * 16,
                 srcA + (size_t)(v * K1_THREADS + tid) * 16);
        const unsigned char* srcB = g_Bt + (size_t)(ncs * 16 + kc) * 32768;
        uint32_t dstB = sb + bufsel * BUFSTRIDE + SB_OFF;
#pragma unroll
        for (int v = 0; v < 4; v++)
            cp16(dstB + (v * K1_THREADS + tid) * 16,
                 srcB + (size_t)(v * K1_THREADS + tid) * 16);
        cp_commit();
    };

    float acc[2][8][4];
#pragma unroll
    for (int mt = 0; mt < 2; mt++)
#pragma unroll
        for (int nt = 0; nt < 8; nt++)
#pragma unroll
            for (int v = 0; v < 4; v++) acc[mt][nt][v] = 0.f;

    stage(0, 0);
    cp_wait0();
    __syncthreads();

    for (int s = 0; s < nsteps; s++) {
        const int cur = s & 1;
        const int u  = blockIdx.x + (s >> 4) * K1_GRID;
        const int tile = u >> 1, ncs = u & 1;
        const int kc = s & 15;
        const uint32_t aB = sb + cur * BUFSTRIDE + SA_OFF;
        const uint32_t bB = sb + cur * BUFSTRIDE + SB_OFF;

        if (s + 1 < nsteps) stage(s + 1, cur ^ 1);

#pragma unroll
        for (int kk = 0; kk < 4; kk++) {
            uint32_t ah[2][4], al[2][4];
#pragma unroll
            for (int mt = 0; mt < 2; mt++) {
                uint32_t off = aoffb + (uint32_t)(mt * 16) * 128u + kk * 32u;
                ldsm4(ah[mt], aB + swz(off));
                ldsm4(al[mt], aB + 16384 + swz(off));
            }
#pragma unroll
            for (int ntp = 0; ntp < 4; ntp++) {
                uint32_t off = boffb + (uint32_t)(ntp * 16) * 128u + kk * 32u;
                uint32_t bh[4];
                ldsm4(bh, bB + swz(off));
#pragma unroll
                for (int mt = 0; mt < 2; mt++) {
                    mma_f16(acc[mt][2 * ntp],     ah[mt], bh[0], bh[1]);
                    mma_f16(acc[mt][2 * ntp],     al[mt], bh[0], bh[1]);
                    mma_f16(acc[mt][2 * ntp + 1], ah[mt], bh[2], bh[3]);
                    mma_f16(acc[mt][2 * ntp + 1], al[mt], bh[2], bh[3]);
                }
            }
        }

        if (kc == 15) {
            const int r0 = tile * 128;
            const int b  = r0 >> 11;
            if (tid < 128) s_sc[tid] = 0.f;
            __syncthreads();
#pragma unroll
            for (int mt = 0; mt < 2; mt++) {
                float p0 = 0.f, p1 = 0.f;
#pragma unroll
                for (int nt = 0; nt < 8; nt++) {
                    int c0 = ncs * 256 + wn * 64 + nt * 8 + q * 2;
                    float d0v = g_D[b * 512 + c0], d1v = g_D[b * 512 + c0 + 1];
                    float w0 = Wa[c0], w1 = Wa[c0 + 1];
                    p0 += tanhf(acc[mt][nt][0] + d0v) * w0 + tanhf(acc[mt][nt][1] + d1v) * w1;
                    p1 += tanhf(acc[mt][nt][2] + d0v) * w0 + tanhf(acc[mt][nt][3] + d1v) * w1;
                }
                p0 += __shfl_xor_sync(0xffffffffu, p0, 1);
                p0 += __shfl_xor_sync(0xffffffffu, p0, 2);
                p1 += __shfl_xor_sync(0xffffffffu, p1, 1);
                p1 += __shfl_xor_sync(0xffffffffu, p1, 2);
                if (q == 0) {
                    atomicAdd(&s_sc[wm * 32 + mt * 16 + r4], p0);
                    atomicAdd(&s_sc[wm * 32 + mt * 16 + r4 + 8], p1);
                }
            }
            __syncthreads();
            if (tid < 128) g_sc2[ncs][r0 + tid] = s_sc[tid];
#pragma unroll
            for (int mt = 0; mt < 2; mt++)
#pragma unroll
                for (int nt = 0; nt < 8; nt++)
#pragma unroll
                    for (int v = 0; v < 4; v++) acc[mt][nt][v] = 0.f;
        }

        cp_wait0();
        __syncthreads();
    }
}

// ------------------------------ k2a: softmax (+mask detect) -----------------
__global__ void k2a_softmax(const unsigned char* __restrict__ masks) {
    int b = blockIdx.x, t = threadIdx.x;
    __shared__ float sm[2048];
    __shared__ float red[256];
    const float NEG_INF = __int_as_float(0xff800000);

    int found = 0;
    for (int j = t; j < 16384; j += 256)
        if (masks[4 * j + 1]) found = 1;
    const int mode = __syncthreads_or(found);   // 1 = byte elems, 0 = 4-byte
    const unsigned int* m32 = (const unsigned int*)masks;

    float lmax = NEG_INF;
#pragma unroll
    for (int v = 0; v < 8; v++) {
        int idx = v * 256 + t;
        float sc = g_sc2[0][b * 2048 + idx] + g_sc2[1][b * 2048 + idx];
        bool masked = mode ? (masks[b * 2048 + idx] != 0) : (m32[b * 2048 + idx] != 0u);
        if (masked) sc = NEG_INF;
        sm[idx] = sc;
        lmax = fmaxf(lmax, sc);
    }
    red[t] = lmax;
    __syncthreads();
    for (int o = 128; o > 0; o >>= 1) {
        if (t < o) red[t] = fmaxf(red[t], red[t + o]);
        __syncthreads();
    }
    float bmax = red[0];
    __syncthreads();

    float lsum = 0.f;
#pragma unroll
    for (int v = 0; v < 8; v++) {
        int idx = v * 256 + t;
        float e = expf(sm[idx] - bmax);
        sm[idx] = e;
        lsum += e;
    }
    red[t] = lsum;
    __syncthreads();
    for (int o = 128; o > 0; o >>= 1) {
        if (t < o) red[t] += red[t + o];
        __syncthreads();
    }
    float inv = 1.f / red[0];
#pragma unroll
    for (int v = 0; v < 8; v++) {
        int idx = v * 256 + t;
        g_weights[b * 2048 + idx] = sm[idx] * inv;
    }
}

// ------------------------------ k2b: compacted weighted sum -----------------
__global__ void k2b_partial(const float* __restrict__ enc) {
    int ch = blockIdx.x, b = blockIdx.y, t = threadIdx.x;
    __shared__ float wv[132];
    __shared__ int   sidx[132];
    __shared__ int   wcnt[4];

    float myw = 0.f;
    int pred = 0;
    if (t < 128) {
        myw = g_weights[b * 2048 + ch * 128 + t];
        pred = (myw != 0.f) ? 1 : 0;
    }
    unsigned bal = __ballot_sync(0xffffffffu, pred);
    if (t < 128 && (t & 31) == 0) wcnt[t >> 5] = __popc(bal);
    __syncthreads();
    int c0 = wcnt[0], c1 = wcnt[1], c2 = wcnt[2], c3 = wcnt[3];
    int cnt = c0 + c1 + c2 + c3;
    int cnt4 = (cnt + 3) & ~3;
    if (t < 128 && pred) {
        int w = t >> 5;
        int off = (w > 0 ? c0 : 0) + (w > 1 ? c1 : 0) + (w > 2 ? c2 : 0);
        off += __popc(bal & ((1u << (t & 31)) - 1u));
        sidx[off] = t;
        wv[off] = myw;
    }
    if (t < cnt4 - cnt) { sidx[cnt + t] = 0; wv[cnt + t] = 0.f; }
    __syncthreads();

    const float4* rowbase =
        reinterpret_cast<const float4*>(enc) + (size_t)(b * 2048 + ch * 128) * 256;
    float4 acc = make_float4(0.f, 0.f, 0.f, 0.f);
    for (int i = 0; i < cnt4; i += 4) {
        int i0 = sidx[i], i1 = sidx[i + 1], i2 = sidx[i + 2], i3 = sidx[i + 3];
        float w0 = wv[i], w1 = wv[i + 1], w2 = wv[i + 2], w3 = wv[i + 3];
        float4 v0 = rowbase[(size_t)i0 * 256 + t];
        float4 v1 = rowbase[(size_t)i1 * 256 + t];
        float4 v2 = rowbase[(size_t)i2 * 256 + t];
        float4 v3 = rowbase[(size_t)i3 * 256 + t];
        acc.x += w0 * v0.x + w1 * v1.x + w2 * v2.x + w3 * v3.x;
        acc.y += w0 * v0.y + w1 * v1.y + w2 * v2.y + w3 * v3.y;
        acc.z += w0 * v0.z + w1 * v1.z + w2 * v2.z + w3 * v3.z;
        acc.w += w0 * v0.w + w1 * v1.w + w2 * v2.w + w3 * v3.w;
    }
    reinterpret_cast<float4*>(g_partial)[(b * NCHUNK + ch) * 256 + t] = acc;
}

// ------------------------------ k2c: final GEMV -----------------------------
__global__ void k2c_context(const float* __restrict__ We,
                            const float* __restrict__ be,
                            float* __restrict__ out) {
    int b = blockIdx.x, t = threadIdx.x;
    __shared__ float ctx[1024];
    float4 s = make_float4(0.f, 0.f, 0.f, 0.f);
#pragma unroll
    for (int chn = 0; chn < NCHUNK; chn++) {
        float4 v = reinterpret_cast<const float4*>(g_partial)[(b * NCHUNK + chn) * 256 + t];
        s.x += v.x; s.y += v.y; s.z += v.z; s.w += v.w;
    }
    reinterpret_cast<float4*>(ctx)[t] = s;
    __syncthreads();

    float acc0 = be[t], acc1 = be[t + 256];
#pragma unroll 4
    for (int k = 0; k < 1024; k++) {
        float c = ctx[k];
        const float* wr = We + k * 512;
        acc0 += c * wr[t];
        acc1 += c * wr[t + 256];
    }
    out[b * 512 + t]       = acc0;
    out[b * 512 + t + 256] = acc1;
}

// ---------------------------------------------------------------------------
extern "C" void kernel_launch(void* const* d_in, const int* in_sizes, int n_in,
                              void* d_out, int out_size) {
    const float*         enc   = (const float*)d_in[0];
    const float*         dec   = (const float*)d_in[1];
    const unsigned char* masks = (const unsigned char*)d_in[2];
    const float*         We    = (const float*)d_in[3];
    const float*         be    = (const float*)d_in[4];
    const float*         Wd    = (const float*)d_in[5];
    const float*         bd    = (const float*)d_in[6];
    const float*         Wa    = (const float*)d_in[7];
    float* out = (float*)d_out;

    static int configured = 0;
    if (!configured) {
        cudaFuncSetAttribute(k1_mma, cudaFuncAttributeMaxDynamicSharedMemorySize, SM_SMEM);
        configured = 1;
    }

    k_prep<<<10304, 256>>>(enc, We, dec, Wd, bd, be);
    k1_mma<<<K1_GRID, K1_THREADS, SM_SMEM>>>(Wa);
    k2a_softmax<<<Bn, 256>>>(masks);
    dim3 g2b(NCHUNK, Bn);
    k2b_partial<<<g2b, 256>>>(enc);
    k2c_context<<<Bn, 256>>>(We, be, out);
}

// round 14
// speedup vs baseline: 1.9859x; 1.3092x over previous
#include <cuda_runtime.h>
#include <cuda_fp16.h>
#include <math.h>
#include <stdint.h>

#define Bn 32
#define Sn 2048
#define NCHUNK 16
#define NTILES 512           // 128-row tiles
#define NUNITS 1024          // (tile, nc) units
#define K1_GRID 148

// ------------------------------ device scratch ------------------------------
__device__ float g_D[Bn * 512];
__device__ float g_sc2[2][Bn * Sn];     // per-nc score partials
__device__ float g_weights[Bn * Sn];
__device__ float g_partial[Bn * NCHUNK * 1024];
// W_enc staged as fp16, SW128-swizzled [n][k] tiles. 32 pieces, each 32KB
__device__ __align__(16) unsigned char g_Bt[32 * 32768];
// enc staged as fp16, swizzled smem-image pieces.
// piece p = rowblock*16 + kc (rowblock 0..511): 16KB
__device__ __align__(16) unsigned char g_At[512 * 16 * 16384ull];

// ------------------------------ helpers -------------------------------------
__device__ __forceinline__ uint32_t smem_u32(const void* p) {
    uint32_t a;
    asm("{ .reg .u64 t; cvta.to.shared.u64 t, %1; cvt.u32.u64 %0, t; }"
        : "=r"(a) : "l"(p));
    return a;
}
__device__ __forceinline__ uint32_t swz(uint32_t off) {
    return off ^ ((off >> 3) & 0x70);
}
__device__ __forceinline__ void ldsm4(uint32_t* r, uint32_t addr) {
    asm volatile("ldmatrix.sync.aligned.m8n8.x4.shared.b16 {%0,%1,%2,%3}, [%4];"
                 : "=r"(r[0]), "=r"(r[1]), "=r"(r[2]), "=r"(r[3]) : "r"(addr));
}
__device__ __forceinline__ void mma_f16(float* c, const uint32_t* a,
                                        uint32_t b0, uint32_t b1) {
    asm("mma.sync.aligned.m16n8k16.row.col.f32.f16.f16.f32 "
        "{%0,%1,%2,%3},{%4,%5,%6,%7},{%8,%9},{%0,%1,%2,%3};"
        : "+f"(c[0]), "+f"(c[1]), "+f"(c[2]), "+f"(c[3])
        : "r"(a[0]), "r"(a[1]), "r"(a[2]), "r"(a[3]), "r"(b0), "r"(b1));
}
__device__ __forceinline__ void cp16(uint32_t dst, const void* src) {
    asm volatile("cp.async.cg.shared.global [%0], [%1], 16;"
                 :: "r"(dst), "l"(src));
}
__device__ __forceinline__ void cp_commit() {
    asm volatile("cp.async.commit_group;" ::: "memory");
}
__device__ __forceinline__ void cp_wait0() {
    asm volatile("cp.async.wait_group 0;" ::: "memory");
}
__device__ __forceinline__ uint32_t pack_half2(__half a, __half b) {
    __half2 h = __halves2half2(a, b);
    return *(uint32_t*)&h;
}

// ------------------------------ k_prep: kA + kW + k0 fused ------------------
// blocks [0,8192): enc conversion; [8192,10240): W_enc staging; [10240,10304): decoder att
__global__ __launch_bounds__(256)
void k_prep(const float* __restrict__ enc, const float* __restrict__ We,
            const float* __restrict__ dec, const float* __restrict__ Wd,
            const float* __restrict__ bd, const float* __restrict__ be) {
    __shared__ float ds[512];
    const int bi = blockIdx.x, tid = threadIdx.x;

    if (bi < 8192) {
        // ---- kA: enc -> fp16 swizzled pieces ----
        int base = bi * 256 + tid;
#pragma unroll
        for (int i = 0; i < 8; i++) {
            int gid = base + i * 2097152;
            int kq = gid & 15;
            int rl = (gid >> 4) & 127;
            int kc = (gid >> 11) & 15;
            int rb = gid >> 15;
            float4 f = ((const float4*)enc)[((size_t)(rb * 128 + rl)) * 256 + kc * 16 + kq];
            __half h0 = __float2half_rn(f.x), h1 = __float2half_rn(f.y);
            __half h2 = __float2half_rn(f.z), h3 = __float2half_rn(f.w);
            unsigned char* basep = g_At + (size_t)(rb * 16 + kc) * 16384;
            uint32_t sw = swz((uint32_t)rl * 128u + (uint32_t)kq * 8u);
            *(uint2*)(basep + sw) = make_uint2(pack_half2(h0, h1), pack_half2(h2, h3));
        }
    } else if (bi < 10240) {
        // ---- kW: W_enc -> fp16 swizzled tiles ----
        int gid = (bi - 8192) * 256 + tid;
        int k = gid >> 9, n = gid & 511;
        float w = We[gid];
        __half hw = __float2half_rn(w);
        int kc = k >> 6, kl = k & 63, nc = n >> 8, nl = n & 255;
        int piece = nc * 16 + kc;
        uint32_t sw = swz((uint32_t)nl * 128u + (uint32_t)kl * 2u);
        *(__half*)(g_Bt + (size_t)piece * 32768 + sw) = hw;
    } else {
        // ---- k0: decoder attention row ----
        int idx = bi - 10240;           // 0..63
        int b = idx >> 1, ah = idx & 1;
        ds[tid]       = dec[b * 512 + tid];
        ds[tid + 256] = dec[b * 512 + tid + 256];
        __syncthreads();
        int a = ah * 256 + tid;
        float acc = be[a] + bd[a];
#pragma unroll 8
        for (int h = 0; h < 512; h++) acc += ds[h] * Wd[h * 512 + a];
        g_D[b * 512 + a] = acc;
    }
}

// ------------------------------ K1: persistent HMMA scores ------------------
#define SA_OFF 0
#define SB_OFF 16384
#define BUFSTRIDE 49152
#define SM_SMEM (2 * BUFSTRIDE)
#define K1_THREADS 512

__global__ __launch_bounds__(K1_THREADS)
void k1_mma(const float* __restrict__ Wa) {
    extern __shared__ char smem[];
    __shared__ float s_sc[128];
    const uint32_t sb = smem_u32(smem);
    const int tid = threadIdx.x;
    const int wid = tid >> 5, lid = tid & 31;
    const int wm = wid & 3;
    const int wn = wid >> 2;
    const int r4 = lid >> 2, q = lid & 3;

    const uint32_t aoffb = (uint32_t)(wm * 32 + (lid & 15)) * 128u + ((lid >> 4) * 16u);
    const uint32_t boffb = (uint32_t)(wn * 64 + (lid & 7) + ((lid >> 4) << 3)) * 128u +
                           (((lid >> 3) & 1) * 16u);

    const int nunits = (NUNITS - blockIdx.x + K1_GRID - 1) / K1_GRID;
    const int nsteps = nunits * 16;

    auto stage = [&](int s, int bufsel) {
        int u  = blockIdx.x + (s >> 4) * K1_GRID;
        int tile = u >> 1, ncs = u & 1;
        int kc = s & 15;
        const unsigned char* srcA = g_At + (size_t)(tile * 16 + kc) * 16384;
        uint32_t dstA = sb + bufsel * BUFSTRIDE + SA_OFF;
#pragma unroll
        for (int v = 0; v < 2; v++)
            cp16(dstA + (v * K1_THREADS + tid) * 16,
                 srcA + (size_t)(v * K1_THREADS + tid) * 16);
        const unsigned char* srcB = g_Bt + (size_t)(ncs * 16 + kc) * 32768;
        uint32_t dstB = sb + bufsel * BUFSTRIDE + SB_OFF;
#pragma unroll
        for (int v = 0; v < 4; v++)
            cp16(dstB + (v * K1_THREADS + tid) * 16,
                 srcB + (size_t)(v * K1_THREADS + tid) * 16);
        cp_commit();
    };

    float acc[2][8][4];
#pragma unroll
    for (int mt = 0; mt < 2; mt++)
#pragma unroll
        for (int nt = 0; nt < 8; nt++)
#pragma unroll
            for (int v = 0; v < 4; v++) acc[mt][nt][v] = 0.f;

    stage(0, 0);
    cp_wait0();
    __syncthreads();

    for (int s = 0; s < nsteps; s++) {
        const int cur = s & 1;
        const int u  = blockIdx.x + (s >> 4) * K1_GRID;
        const int tile = u >> 1, ncs = u & 1;
        const int kc = s & 15;
        const uint32_t aB = sb + cur * BUFSTRIDE + SA_OFF;
        const uint32_t bB = sb + cur * BUFSTRIDE + SB_OFF;

        if (s + 1 < nsteps) stage(s + 1, cur ^ 1);

#pragma unroll
        for (int kk = 0; kk < 4; kk++) {
            uint32_t ah[2][4];
#pragma unroll
            for (int mt = 0; mt < 2; mt++) {
                uint32_t off = aoffb + (uint32_t)(mt * 16) * 128u + kk * 32u;
                ldsm4(ah[mt], aB + swz(off));
            }
#pragma unroll
            for (int ntp = 0; ntp < 4; ntp++) {
                uint32_t off = boffb + (uint32_t)(ntp * 16) * 128u + kk * 32u;
                uint32_t bh[4];
                ldsm4(bh, bB + swz(off));
#pragma unroll
                for (int mt = 0; mt < 2; mt++) {
                    mma_f16(acc[mt][2 * ntp],     ah[mt], bh[0], bh[1]);
                    mma_f16(acc[mt][2 * ntp + 1], ah[mt], bh[2], bh[3]);
                }
            }
        }

        if (kc == 15) {
            const int r0 = tile * 128;
            const int b  = r0 >> 11;
            if (tid < 128) s_sc[tid] = 0.f;
            __syncthreads();
#pragma unroll
            for (int mt = 0; mt < 2; mt++) {
                float p0 = 0.f, p1 = 0.f;
#pragma unroll
                for (int nt = 0; nt < 8; nt++) {
                    int c0 = ncs * 256 + wn * 64 + nt * 8 + q * 2;
                    float d0v = g_D[b * 512 + c0], d1v = g_D[b * 512 + c0 + 1];
                    float w0 = Wa[c0], w1 = Wa[c0 + 1];
                    p0 += tanhf(acc[mt][nt][0] + d0v) * w0 + tanhf(acc[mt][nt][1] + d1v) * w1;
                    p1 += tanhf(acc[mt][nt][2] + d0v) * w0 + tanhf(acc[mt][nt][3] + d1v) * w1;
                }
                p0 += __shfl_xor_sync(0xffffffffu, p0, 1);
                p0 += __shfl_xor_sync(0xffffffffu, p0, 2);
                p1 += __shfl_xor_sync(0xffffffffu, p1, 1);
                p1 += __shfl_xor_sync(0xffffffffu, p1, 2);
                if (q == 0) {
                    atomicAdd(&s_sc[wm * 32 + mt * 16 + r4], p0);
                    atomicAdd(&s_sc[wm * 32 + mt * 16 + r4 + 8], p1);
                }
            }
            __syncthreads();
            if (tid < 128) g_sc2[ncs][r0 + tid] = s_sc[tid];
#pragma unroll
            for (int mt = 0; mt < 2; mt++)
#pragma unroll
                for (int nt = 0; nt < 8; nt++)
#pragma unroll
                    for (int v = 0; v < 4; v++) acc[mt][nt][v] = 0.f;
        }

        cp_wait0();
        __syncthreads();
    }
}

// ------------------------------ k2a: softmax (+mask detect) -----------------
__global__ void k2a_softmax(const unsigned char* __restrict__ masks) {
    int b = blockIdx.x, t = threadIdx.x;
    __shared__ float sm[2048];
    __shared__ float red[256];
    const float NEG_INF = __int_as_float(0xff800000);

    int found = 0;
    for (int j = t; j < 16384; j += 256)
        if (masks[4 * j + 1]) found = 1;
    const int mode = __syncthreads_or(found);   // 1 = byte elems, 0 = 4-byte
    const unsigned int* m32 = (const unsigned int*)masks;

    float lmax = NEG_INF;
#pragma unroll
    for (int v = 0; v < 8; v++) {
        int idx = v * 256 + t;
        float sc = g_sc2[0][b * 2048 + idx] + g_sc2[1][b * 2048 + idx];
        bool masked = mode ? (masks[b * 2048 + idx] != 0) : (m32[b * 2048 + idx] != 0u);
        if (masked) sc = NEG_INF;
        sm[idx] = sc;
        lmax = fmaxf(lmax, sc);
    }
    red[t] = lmax;
    __syncthreads();
    for (int o = 128; o > 0; o >>= 1) {
        if (t < o) red[t] = fmaxf(red[t], red[t + o]);
        __syncthreads();
    }
    float bmax = red[0];
    __syncthreads();

    float lsum = 0.f;
#pragma unroll
    for (int v = 0; v < 8; v++) {
        int idx = v * 256 + t;
        float e = expf(sm[idx] - bmax);
        sm[idx] = e;
        lsum += e;
    }
    red[t] = lsum;
    __syncthreads();
    for (int o = 128; o > 0; o >>= 1) {
        if (t < o) red[t] += red[t + o];
        __syncthreads();
    }
    float inv = 1.f / red[0];
#pragma unroll
    for (int v = 0; v < 8; v++) {
        int idx = v * 256 + t;
        g_weights[b * 2048 + idx] = sm[idx] * inv;
    }
}

// ------------------------------ k2b: compacted weighted sum -----------------
__global__ void k2b_partial(const float* __restrict__ enc) {
    int ch = blockIdx.x, b = blockIdx.y, t = threadIdx.x;
    __shared__ float wv[132];
    __shared__ int   sidx[132];
    __shared__ int   wcnt[4];

    float myw = 0.f;
    int pred = 0;
    if (t < 128) {
        myw = g_weights[b * 2048 + ch * 128 + t];
        pred = (myw != 0.f) ? 1 : 0;
    }
    unsigned bal = __ballot_sync(0xffffffffu, pred);
    if (t < 128 && (t & 31) == 0) wcnt[t >> 5] = __popc(bal);
    __syncthreads();
    int c0 = wcnt[0], c1 = wcnt[1], c2 = wcnt[2], c3 = wcnt[3];
    int cnt = c0 + c1 + c2 + c3;
    int cnt4 = (cnt + 3) & ~3;
    if (t < 128 && pred) {
        int w = t >> 5;
        int off = (w > 0 ? c0 : 0) + (w > 1 ? c1 : 0) + (w > 2 ? c2 : 0);
        off += __popc(bal & ((1u << (t & 31)) - 1u));
        sidx[off] = t;
        wv[off] = myw;
    }
    if (t < cnt4 - cnt) { sidx[cnt + t] = 0; wv[cnt + t] = 0.f; }
    __syncthreads();

    const float4* rowbase =
        reinterpret_cast<const float4*>(enc) + (size_t)(b * 2048 + ch * 128) * 256;
    float4 acc = make_float4(0.f, 0.f, 0.f, 0.f);
    for (int i = 0; i < cnt4; i += 4) {
        int i0 = sidx[i], i1 = sidx[i + 1], i2 = sidx[i + 2], i3 = sidx[i + 3];
        float w0 = wv[i], w1 = wv[i + 1], w2 = wv[i + 2], w3 = wv[i + 3];
        float4 v0 = rowbase[(size_t)i0 * 256 + t];
        float4 v1 = rowbase[(size_t)i1 * 256 + t];
        float4 v2 = rowbase[(size_t)i2 * 256 + t];
        float4 v3 = rowbase[(size_t)i3 * 256 + t];
        acc.x += w0 * v0.x + w1 * v1.x + w2 * v2.x + w3 * v3.x;
        acc.y += w0 * v0.y + w1 * v1.y + w2 * v2.y + w3 * v3.y;
        acc.z += w0 * v0.z + w1 * v1.z + w2 * v2.z + w3 * v3.z;
        acc.w += w0 * v0.w + w1 * v1.w + w2 * v2.w + w3 * v3.w;
    }
    reinterpret_cast<float4*>(g_partial)[(b * NCHUNK + ch) * 256 + t] = acc;
}

// ------------------------------ k2c: final GEMV -----------------------------
__global__ void k2c_context(const float* __restrict__ We,
                            const float* __restrict__ be,
                            float* __restrict__ out) {
    int b = blockIdx.x, t = threadIdx.x;
    __shared__ float ctx[1024];
    float4 s = make_float4(0.f, 0.f, 0.f, 0.f);
#pragma unroll
    for (int chn = 0; chn < NCHUNK; chn++) {
        float4 v = reinterpret_cast<const float4*>(g_partial)[(b * NCHUNK + chn) * 256 + t];
        s.x += v.x; s.y += v.y; s.z += v.z; s.w += v.w;
    }
    reinterpret_cast<float4*>(ctx)[t] = s;
    __syncthreads();

    float acc0 = be[t], acc1 = be[t + 256];
#pragma unroll 4
    for (int k = 0; k < 1024; k++) {
        float c = ctx[k];
        const float* wr = We + k * 512;
        acc0 += c * wr[t];
        acc1 += c * wr[t + 256];
    }
    out[b * 512 + t]       = acc0;
    out[b * 512 + t + 256] = acc1;
}

// ---------------------------------------------------------------------------
extern "C" void kernel_launch(void* const* d_in, const int* in_sizes, int n_in,
                              void* d_out, int out_size) {
    const float*         enc   = (const float*)d_in[0];
    const float*         dec   = (const float*)d_in[1];
    const unsigned char* masks = (const unsigned char*)d_in[2];
    const float*         We    = (const float*)d_in[3];
    const float*         be    = (const float*)d_in[4];
    const float*         Wd    = (const float*)d_in[5];
    const float*         bd    = (const float*)d_in[6];
    const float*         Wa    = (const float*)d_in[7];
    float* out = (float*)d_out;

    static int configured = 0;
    if (!configured) {
        cudaFuncSetAttribute(k1_mma, cudaFuncAttributeMaxDynamicSharedMemorySize, SM_SMEM);
        configured = 1;
    }

    k_prep<<<10304, 256>>>(enc, We, dec, Wd, bd, be);
    k1_mma<<<K1_GRID, K1_THREADS, SM_SMEM>>>(Wa);
    k2a_softmax<<<Bn, 256>>>(masks);
    dim3 g2b(NCHUNK, Bn);
    k2b_partial<<<g2b, 256>>>(enc);
    k2c_context<<<Bn, 256>>>(We, be, out);
}

// round 15
// speedup vs baseline: 2.3168x; 1.1666x over previous
#include <cuda_runtime.h>
#include <cuda_fp16.h>
#include <math.h>
#include <stdint.h>

#define Bn 32
#define Sn 2048
#define NCHUNK 16
#define TPB 9                 // tiles per batch (capacity 1152 rows, cnt~1024)
#define NUNITS (Bn * TPB * 2) // 576 (tile, nc) units
#define K1_GRID 148

// ------------------------------ device scratch ------------------------------
__device__ float g_D[Bn * 512];
__device__ float g_sc2[2][Bn * 1152];   // per-nc compacted score partials
__device__ float g_weights[Bn * Sn];
__device__ float g_partial[Bn * NCHUNK * 1024];
__device__ int   g_idx[Bn * 1152];      // compacted unmasked row indices
__device__ int   g_cnt[Bn];
// W_enc staged as fp16, SW128-swizzled [n][k] tiles. 32 pieces, each 32KB
__device__ __align__(16) unsigned char g_Bt[32 * 32768];

// ------------------------------ helpers -------------------------------------
__device__ __forceinline__ uint32_t smem_u32(const void* p) {
    uint32_t a;
    asm("{ .reg .u64 t; cvta.to.shared.u64 t, %1; cvt.u32.u64 %0, t; }"
        : "=r"(a) : "l"(p));
    return a;
}
__device__ __forceinline__ uint32_t swz(uint32_t off) {
    return off ^ ((off >> 3) & 0x70);
}
__device__ __forceinline__ void ldsm4(uint32_t* r, uint32_t addr) {
    asm volatile("ldmatrix.sync.aligned.m8n8.x4.shared.b16 {%0,%1,%2,%3}, [%4];"
                 : "=r"(r[0]), "=r"(r[1]), "=r"(r[2]), "=r"(r[3]) : "r"(addr));
}
__device__ __forceinline__ void mma_f16(float* c, const uint32_t* a,
                                        uint32_t b0, uint32_t b1) {
    asm("mma.sync.aligned.m16n8k16.row.col.f32.f16.f16.f32 "
        "{%0,%1,%2,%3},{%4,%5,%6,%7},{%8,%9},{%0,%1,%2,%3};"
        : "+f"(c[0]), "+f"(c[1]), "+f"(c[2]), "+f"(c[3])
        : "r"(a[0]), "r"(a[1]), "r"(a[2]), "r"(a[3]), "r"(b0), "r"(b1));
}
__device__ __forceinline__ void cp16(uint32_t dst, const void* src) {
    asm volatile("cp.async.cg.shared.global [%0], [%1], 16;"
                 :: "r"(dst), "l"(src));
}
__device__ __forceinline__ void cp_commit() {
    asm volatile("cp.async.commit_group;" ::: "memory");
}
__device__ __forceinline__ void cp_wait0() {
    asm volatile("cp.async.wait_group 0;" ::: "memory");
}
__device__ __forceinline__ uint32_t pack_half2(__half a, __half b) {
    __half2 h = __halves2half2(a, b);
    return *(uint32_t*)&h;
}

// ------------------------------ k_prep --------------------------------------
// blocks [0,2048): kW staging; [2048,2112): k0 decoder; [2112,2144): compaction
__global__ __launch_bounds__(256)
void k_prep(const float* __restrict__ We, const float* __restrict__ dec,
            const float* __restrict__ Wd, const float* __restrict__ bd,
            const float* __restrict__ be, const unsigned char* __restrict__ masks) {
    __shared__ float ds[512];
    __shared__ int   wsum[8];
    const int bi = blockIdx.x, tid = threadIdx.x;

    if (bi < 2048) {
        // ---- kW: W_enc -> fp16 swizzled tiles ----
        int gid = bi * 256 + tid;
        int k = gid >> 9, n = gid & 511;
        __half hw = __float2half_rn(We[gid]);
        int kc = k >> 6, kl = k & 63, nc = n >> 8, nl = n & 255;
        int piece = nc * 16 + kc;
        uint32_t sw = swz((uint32_t)nl * 128u + (uint32_t)kl * 2u);
        *(__half*)(g_Bt + (size_t)piece * 32768 + sw) = hw;
    } else if (bi < 2112) {
        // ---- k0: decoder attention row ----
        int idx = bi - 2048;            // 0..63
        int b = idx >> 1, ah = idx & 1;
        ds[tid]       = dec[b * 512 + tid];
        ds[tid + 256] = dec[b * 512 + tid + 256];
        __syncthreads();
        int a = ah * 256 + tid;
        float acc = be[a] + bd[a];
#pragma unroll 8
        for (int h = 0; h < 512; h++) acc += ds[h] * Wd[h * 512 + a];
        g_D[b * 512 + a] = acc;
    } else {
        // ---- compaction: one block per batch ----
        int b = bi - 2112;
        // detect mask element width (same rule as before, sampled over 64KB)
        int found = 0;
        for (int j = tid; j < 16384; j += 256)
            if (masks[4 * j + 1]) found = 1;
        const int mode = __syncthreads_or(found); // 1 = byte elems, 0 = 4-byte
        const unsigned int* m32 = (const unsigned int*)masks;

        // each thread owns 8 consecutive positions -> ascending order preserved
        int keep[8], c = 0;
#pragma unroll
        for (int j = 0; j < 8; j++) {
            int i = tid * 8 + j;
            bool masked = mode ? (masks[b * 2048 + i] != 0)
                               : (m32[b * 2048 + i] != 0u);
            keep[j] = masked ? 0 : 1;
            c += keep[j];
        }
        // exclusive prefix over 256 threads
        int lane = tid & 31, w = tid >> 5;
        int incl = c;
#pragma unroll
        for (int o = 1; o < 32; o <<= 1) {
            int v = __shfl_up_sync(0xffffffffu, incl, o);
            if (lane >= o) incl += v;
        }
        if (lane == 31) wsum[w] = incl;
        __syncthreads();
        int woff = 0;
#pragma unroll
        for (int ww = 0; ww < 8; ww++) if (ww < w) woff += wsum[ww];
        int pos = woff + incl - c;      // exclusive prefix
        int total = 0;
#pragma unroll
        for (int ww = 0; ww < 8; ww++) total += wsum[ww];
#pragma unroll
        for (int j = 0; j < 8; j++) {
            if (keep[j]) g_idx[b * 1152 + pos++] = tid * 8 + j;
        }
        if (tid == 0) g_cnt[b] = total;
        // pad remainder with row 0
        for (int i = total + tid; i < 1152; i += 256) g_idx[b * 1152 + i] = 0;
    }
}

// ------------------------------ K1: persistent HMMA scores ------------------
// buffer = A 16KB + B 32KB = 48KB; 2 buffers = 96KB
#define SA_OFF 0
#define SB_OFF 16384
#define BUFSTRIDE 49152
#define SM_SMEM (2 * BUFSTRIDE)
#define K1_THREADS 512

__global__ __launch_bounds__(K1_THREADS)
void k1_mma(const float* __restrict__ enc, const float* __restrict__ Wa) {
    extern __shared__ char smem[];
    __shared__ float s_sc[128];
    const uint32_t sb = smem_u32(smem);
    const int tid = threadIdx.x;
    const int wid = tid >> 5, lid = tid & 31;
    const int bid = blockIdx.x;
    const int wm = wid & 3;
    const int wn = wid >> 2;
    const int r4 = lid >> 2, q = lid & 3;

    const uint32_t aoffb = (uint32_t)(wm * 32 + (lid & 15)) * 128u + ((lid >> 4) * 16u);
    const uint32_t boffb = (uint32_t)(wn * 64 + (lid & 7) + ((lid >> 4) << 3)) * 128u +
                           (((lid >> 3) & 1) * 16u);

    const int nunits = (NUNITS - bid + K1_GRID - 1) / K1_GRID;
    const int nsteps = nunits * 16;

    float4 arA[2][4];

    // gather-load A piece for step s into reg set
    auto ldgA = [&](int s, float4* ar) {
        int u = bid + (s >> 4) * K1_GRID;
        int tile = u >> 1;
        int b = tile / TPB, ti = tile - b * TPB;
        int kc = s & 15;
        const int* idxp = g_idx + b * 1152 + ti * 128;
        const float4* srcb = (const float4*)enc + (size_t)b * 2048 * 256 + kc * 16;
#pragma unroll
        for (int v = 0; v < 4; v++) {
            int i = v * K1_THREADS + tid;
            int row = i >> 4, kq = i & 15;
            int gr = idxp[row];
            ar[v] = srcb[(size_t)gr * 256 + kq];
        }
    };
    // convert + store A piece into smem buffer
    auto stsA = [&](const float4* ar, int buf) {
        char* abuf = smem + buf * BUFSTRIDE + SA_OFF;
#pragma unroll
        for (int v = 0; v < 4; v++) {
            int i = v * K1_THREADS + tid;
            int row = i >> 4, kq = i & 15;
            float4 f = ar[v];
            uint32_t p0 = pack_half2(__float2half_rn(f.x), __float2half_rn(f.y));
            uint32_t p1 = pack_half2(__float2half_rn(f.z), __float2half_rn(f.w));
            uint32_t sw = swz((uint32_t)row * 128u + (uint32_t)kq * 8u);
            *(uint2*)(abuf + sw) = make_uint2(p0, p1);
        }
    };
    auto cpB = [&](int s, int buf) {
        int u = bid + (s >> 4) * K1_GRID;
        int ncs = u & 1;
        int kc = s & 15;
        const unsigned char* srcB = g_Bt + (size_t)(ncs * 16 + kc) * 32768;
        uint32_t dst = sb + buf * BUFSTRIDE + SB_OFF;
#pragma unroll
        for (int v = 0; v < 4; v++)
            cp16(dst + (v * K1_THREADS + tid) * 16,
                 srcB + (size_t)(v * K1_THREADS + tid) * 16);
        cp_commit();
    };

    float acc[2][8][4];
#pragma unroll
    for (int mt = 0; mt < 2; mt++)
#pragma unroll
        for (int nt = 0; nt < 8; nt++)
#pragma unroll
            for (int v = 0; v < 4; v++) acc[mt][nt][v] = 0.f;

    // prologue
    ldgA(0, arA[0]);
    cpB(0, 0);
    if (nsteps > 1) ldgA(1, arA[1]);
    stsA(arA[0], 0);
    cp_wait0();
    __syncthreads();

    for (int s = 0; s < nsteps; s++) {
        const int cur = s & 1;
        const int u  = bid + (s >> 4) * K1_GRID;
        const int tile = u >> 1, ncs = u & 1;
        const int kc = s & 15;
        const uint32_t aB = sb + cur * BUFSTRIDE + SA_OFF;
        const uint32_t bB = sb + cur * BUFSTRIDE + SB_OFF;

        if (s + 1 < nsteps) {
            stsA(arA[(s + 1) & 1], cur ^ 1);     // A(s+1) -> free buffer
            if (s + 2 < nsteps) ldgA(s + 2, arA[s & 1]); // reuse set of consumed A(s)
            cpB(s + 1, cur ^ 1);
        }

#pragma unroll
        for (int kk = 0; kk < 4; kk++) {
            uint32_t ah[2][4];
#pragma unroll
            for (int mt = 0; mt < 2; mt++) {
                uint32_t off = aoffb + (uint32_t)(mt * 16) * 128u + kk * 32u;
                ldsm4(ah[mt], aB + swz(off));
            }
#pragma unroll
            for (int ntp = 0; ntp < 4; ntp++) {
                uint32_t off = boffb + (uint32_t)(ntp * 16) * 128u + kk * 32u;
                uint32_t bh[4];
                ldsm4(bh, bB + swz(off));
#pragma unroll
                for (int mt = 0; mt < 2; mt++) {
                    mma_f16(acc[mt][2 * ntp],     ah[mt], bh[0], bh[1]);
                    mma_f16(acc[mt][2 * ntp + 1], ah[mt], bh[2], bh[3]);
                }
            }
        }

        if (kc == 15) {
            const int b = tile / TPB;
            if (tid < 128) s_sc[tid] = 0.f;
            __syncthreads();
#pragma unroll
            for (int mt = 0; mt < 2; mt++) {
                float p0 = 0.f, p1 = 0.f;
#pragma unroll
                for (int nt = 0; nt < 8; nt++) {
                    int c0 = ncs * 256 + wn * 64 + nt * 8 + q * 2;
                    float d0v = g_D[b * 512 + c0], d1v = g_D[b * 512 + c0 + 1];
                    float w0 = Wa[c0], w1 = Wa[c0 + 1];
                    p0 += tanhf(acc[mt][nt][0] + d0v) * w0 + tanhf(acc[mt][nt][1] + d1v) * w1;
                    p1 += tanhf(acc[mt][nt][2] + d0v) * w0 + tanhf(acc[mt][nt][3] + d1v) * w1;
                }
                p0 += __shfl_xor_sync(0xffffffffu, p0, 1);
                p0 += __shfl_xor_sync(0xffffffffu, p0, 2);
                p1 += __shfl_xor_sync(0xffffffffu, p1, 1);
                p1 += __shfl_xor_sync(0xffffffffu, p1, 2);
                if (q == 0) {
                    atomicAdd(&s_sc[wm * 32 + mt * 16 + r4], p0);
                    atomicAdd(&s_sc[wm * 32 + mt * 16 + r4 + 8], p1);
                }
            }
            __syncthreads();
            if (tid < 128) g_sc2[ncs][tile * 128 + tid] = s_sc[tid];
#pragma unroll
            for (int mt = 0; mt < 2; mt++)
#pragma unroll
                for (int nt = 0; nt < 8; nt++)
#pragma unroll
                    for (int v = 0; v < 4; v++) acc[mt][nt][v] = 0.f;
        }

        cp_wait0();
        __syncthreads();
    }
}

// ------------------------------ k2a: compacted softmax + scatter ------------
__global__ void k2a_softmax() {
    int b = blockIdx.x, t = threadIdx.x;
    __shared__ float sm[1152];
    __shared__ float red[256];
    const float NEG_INF = __int_as_float(0xff800000);
    const int cnt = g_cnt[b];

    float lmax = NEG_INF;
#pragma unroll
    for (int v = 0; v < 5; v++) {
        int i = v * 256 + t;
        if (i < cnt) {
            float sc = g_sc2[0][b * 1152 + i] + g_sc2[1][b * 1152 + i];
            sm[i] = sc;
            lmax = fmaxf(lmax, sc);
        }
    }
    red[t] = lmax;
    __syncthreads();
    for (int o = 128; o > 0; o >>= 1) {
        if (t < o) red[t] = fmaxf(red[t], red[t + o]);
        __syncthreads();
    }
    float bmax = red[0];
    __syncthreads();

    float lsum = 0.f;
#pragma unroll
    for (int v = 0; v < 5; v++) {
        int i = v * 256 + t;
        if (i < cnt) {
            float e = expf(sm[i] - bmax);
            sm[i] = e;
            lsum += e;
        }
    }
    red[t] = lsum;
    __syncthreads();
    for (int o = 128; o > 0; o >>= 1) {
        if (t < o) red[t] += red[t + o];
        __syncthreads();
    }
    float inv = 1.f / red[0];

    // zero full weight row, then scatter compacted weights
#pragma unroll
    for (int v = 0; v < 8; v++) g_weights[b * 2048 + v * 256 + t] = 0.f;
    __syncthreads();
#pragma unroll
    for (int v = 0; v < 5; v++) {
        int i = v * 256 + t;
        if (i < cnt) g_weights[b * 2048 + g_idx[b * 1152 + i]] = sm[i] * inv;
    }
}

// ------------------------------ k2b: compacted weighted sum -----------------
__global__ void k2b_partial(const float* __restrict__ enc) {
    int ch = blockIdx.x, b = blockIdx.y, t = threadIdx.x;
    __shared__ float wv[132];
    __shared__ int   sidx[132];
    __shared__ int   wcnt[4];

    float myw = 0.f;
    int pred = 0;
    if (t < 128) {
        myw = g_weights[b * 2048 + ch * 128 + t];
        pred = (myw != 0.f) ? 1 : 0;
    }
    unsigned bal = __ballot_sync(0xffffffffu, pred);
    if (t < 128 && (t & 31) == 0) wcnt[t >> 5] = __popc(bal);
    __syncthreads();
    int c0 = wcnt[0], c1 = wcnt[1], c2 = wcnt[2], c3 = wcnt[3];
    int cnt = c0 + c1 + c2 + c3;
    int cnt4 = (cnt + 3) & ~3;
    if (t < 128 && pred) {
        int w = t >> 5;
        int off = (w > 0 ? c0 : 0) + (w > 1 ? c1 : 0) + (w > 2 ? c2 : 0);
        off += __popc(bal & ((1u << (t & 31)) - 1u));
        sidx[off] = t;
        wv[off] = myw;
    }
    if (t < cnt4 - cnt) { sidx[cnt + t] = 0; wv[cnt + t] = 0.f; }
    __syncthreads();

    const float4* rowbase =
        reinterpret_cast<const float4*>(enc) + (size_t)(b * 2048 + ch * 128) * 256;
    float4 acc = make_float4(0.f, 0.f, 0.f, 0.f);
    for (int i = 0; i < cnt4; i += 4) {
        int i0 = sidx[i], i1 = sidx[i + 1], i2 = sidx[i + 2], i3 = sidx[i + 3];
        float w0 = wv[i], w1 = wv[i + 1], w2 = wv[i + 2], w3 = wv[i + 3];
        float4 v0 = rowbase[(size_t)i0 * 256 + t];
        float4 v1 = rowbase[(size_t)i1 * 256 + t];
        float4 v2 = rowbase[(size_t)i2 * 256 + t];
        float4 v3 = rowbase[(size_t)i3 * 256 + t];
        acc.x += w0 * v0.x + w1 * v1.x + w2 * v2.x + w3 * v3.x;
        acc.y += w0 * v0.y + w1 * v1.y + w2 * v2.y + w3 * v3.y;
        acc.z += w0 * v0.z + w1 * v1.z + w2 * v2.z + w3 * v3.z;
        acc.w += w0 * v0.w + w1 * v1.w + w2 * v2.w + w3 * v3.w;
    }
    reinterpret_cast<float4*>(g_partial)[(b * NCHUNK + ch) * 256 + t] = acc;
}

// ------------------------------ k2c: final GEMV -----------------------------
__global__ void k2c_context(const float* __restrict__ We,
                            const float* __restrict__ be,
                            float* __restrict__ out) {
    int b = blockIdx.x, t = threadIdx.x;
    __shared__ float ctx[1024];
    float4 s = make_float4(0.f, 0.f, 0.f, 0.f);
#pragma unroll
    for (int chn = 0; chn < NCHUNK; chn++) {
        float4 v = reinterpret_cast<const float4*>(g_partial)[(b * NCHUNK + chn) * 256 + t];
        s.x += v.x; s.y += v.y; s.z += v.z; s.w += v.w;
    }
    reinterpret_cast<float4*>(ctx)[t] = s;
    __syncthreads();

    float acc0 = be[t], acc1 = be[t + 256];
#pragma unroll 4
    for (int k = 0; k < 1024; k++) {
        float c = ctx[k];
        const float* wr = We + k * 512;
        acc0 += c * wr[t];
        acc1 += c * wr[t + 256];
    }
    out[b * 512 + t]       = acc0;
    out[b * 512 + t + 256] = acc1;
}

// ---------------------------------------------------------------------------
extern "C" void kernel_launch(void* const* d_in, const int* in_sizes, int n_in,
                              void* d_out, int out_size) {
    const float*         enc   = (const float*)d_in[0];
    const float*         dec   = (const float*)d_in[1];
    const unsigned char* masks = (const unsigned char*)d_in[2];
    const float*         We    = (const float*)d_in[3];
    const float*         be    = (const float*)d_in[4];
    const float*         Wd    = (const float*)d_in[5];
    const float*         bd    = (const float*)d_in[6];
    const float*         Wa    = (const float*)d_in[7];
    float* out = (float*)d_out;

    static int configured = 0;
    if (!configured) {
        cudaFuncSetAttribute(k1_mma, cudaFuncAttributeMaxDynamicSharedMemorySize, SM_SMEM);
        configured = 1;
    }

    k_prep<<<2144, 256>>>(We, dec, Wd, bd, be, masks);
    k1_mma<<<K1_GRID, K1_THREADS, SM_SMEM>>>(enc, Wa);
    k2a_softmax<<<Bn, 256>>>();
    dim3 g2b(NCHUNK, Bn);
    k2b_partial<<<g2b, 256>>>(enc);
    k2c_context<<<Bn, 256>>>(We, be, out);
}

// round 16
// speedup vs baseline: 2.6230x; 1.1321x over previous
#include <cuda_runtime.h>
#include <cuda_fp16.h>
#include <math.h>
#include <stdint.h>

#define Bn 32
#define Sn 2048
#define NCHUNK 9              // compacted chunks of 128 (capacity 1152)
#define TPB 9                 // tiles per batch
#define NUNITS (Bn * TPB * 2) // 576 (tile, nc) units
#define K1_GRID 148

// ------------------------------ device scratch ------------------------------
__device__ float g_D[Bn * 512];
__device__ float g_sc2[2][Bn * 1152];   // per-nc compacted score partials
__device__ float g_wc[Bn * 1152];       // compacted softmax weights
__device__ float g_partial[Bn * NCHUNK * 1024];
__device__ int   g_idx[Bn * 1152];      // compacted unmasked row indices
__device__ int   g_cnt[Bn];
// W_enc staged as fp16, SW128-swizzled [n][k] tiles. 32 pieces, each 32KB
__device__ __align__(16) unsigned char g_Bt[32 * 32768];

// ------------------------------ helpers -------------------------------------
__device__ __forceinline__ uint32_t smem_u32(const void* p) {
    uint32_t a;
    asm("{ .reg .u64 t; cvta.to.shared.u64 t, %1; cvt.u32.u64 %0, t; }"
        : "=r"(a) : "l"(p));
    return a;
}
__device__ __forceinline__ uint32_t swz(uint32_t off) {
    return off ^ ((off >> 3) & 0x70);
}
__device__ __forceinline__ void ldsm4(uint32_t* r, uint32_t addr) {
    asm volatile("ldmatrix.sync.aligned.m8n8.x4.shared.b16 {%0,%1,%2,%3}, [%4];"
                 : "=r"(r[0]), "=r"(r[1]), "=r"(r[2]), "=r"(r[3]) : "r"(addr));
}
__device__ __forceinline__ void mma_f16(float* c, const uint32_t* a,
                                        uint32_t b0, uint32_t b1) {
    asm("mma.sync.aligned.m16n8k16.row.col.f32.f16.f16.f32 "
        "{%0,%1,%2,%3},{%4,%5,%6,%7},{%8,%9},{%0,%1,%2,%3};"
        : "+f"(c[0]), "+f"(c[1]), "+f"(c[2]), "+f"(c[3])
        : "r"(a[0]), "r"(a[1]), "r"(a[2]), "r"(a[3]), "r"(b0), "r"(b1));
}
__device__ __forceinline__ void cp16(uint32_t dst, const void* src) {
    asm volatile("cp.async.cg.shared.global [%0], [%1], 16;"
                 :: "r"(dst), "l"(src));
}
__device__ __forceinline__ void cp_commit() {
    asm volatile("cp.async.commit_group;" ::: "memory");
}
__device__ __forceinline__ void cp_wait0() {
    asm volatile("cp.async.wait_group 0;" ::: "memory");
}
__device__ __forceinline__ uint32_t pack_half2(__half a, __half b) {
    __half2 h = __halves2half2(a, b);
    return *(uint32_t*)&h;
}

// ------------------------------ k_prep --------------------------------------
// blocks [0,2048): kW staging; [2048,2112): k0 decoder; [2112,2144): compaction
__global__ __launch_bounds__(256)
void k_prep(const float* __restrict__ We, const float* __restrict__ dec,
            const float* __restrict__ Wd, const float* __restrict__ bd,
            const float* __restrict__ be, const unsigned char* __restrict__ masks) {
    __shared__ float ds[512];
    __shared__ int   wsum[8];
    const int bi = blockIdx.x, tid = threadIdx.x;

    if (bi < 2048) {
        int gid = bi * 256 + tid;
        int k = gid >> 9, n = gid & 511;
        __half hw = __float2half_rn(We[gid]);
        int kc = k >> 6, kl = k & 63, nc = n >> 8, nl = n & 255;
        int piece = nc * 16 + kc;
        uint32_t sw = swz((uint32_t)nl * 128u + (uint32_t)kl * 2u);
        *(__half*)(g_Bt + (size_t)piece * 32768 + sw) = hw;
    } else if (bi < 2112) {
        int idx = bi - 2048;
        int b = idx >> 1, ah = idx & 1;
        ds[tid]       = dec[b * 512 + tid];
        ds[tid + 256] = dec[b * 512 + tid + 256];
        __syncthreads();
        int a = ah * 256 + tid;
        float acc = be[a] + bd[a];
#pragma unroll 8
        for (int h = 0; h < 512; h++) acc += ds[h] * Wd[h * 512 + a];
        g_D[b * 512 + a] = acc;
    } else {
        int b = bi - 2112;
        int found = 0;
        for (int j = tid; j < 16384; j += 256)
            if (masks[4 * j + 1]) found = 1;
        const int mode = __syncthreads_or(found); // 1 = byte elems, 0 = 4-byte
        const unsigned int* m32 = (const unsigned int*)masks;

        int keep[8], c = 0;
#pragma unroll
        for (int j = 0; j < 8; j++) {
            int i = tid * 8 + j;
            bool masked = mode ? (masks[b * 2048 + i] != 0)
                               : (m32[b * 2048 + i] != 0u);
            keep[j] = masked ? 0 : 1;
            c += keep[j];
        }
        int lane = tid & 31, w = tid >> 5;
        int incl = c;
#pragma unroll
        for (int o = 1; o < 32; o <<= 1) {
            int v = __shfl_up_sync(0xffffffffu, incl, o);
            if (lane >= o) incl += v;
        }
        if (lane == 31) wsum[w] = incl;
        __syncthreads();
        int woff = 0;
#pragma unroll
        for (int ww = 0; ww < 8; ww++) if (ww < w) woff += wsum[ww];
        int pos = woff + incl - c;
        int total = 0;
#pragma unroll
        for (int ww = 0; ww < 8; ww++) total += wsum[ww];
#pragma unroll
        for (int j = 0; j < 8; j++) {
            if (keep[j]) g_idx[b * 1152 + pos++] = tid * 8 + j;
        }
        if (tid == 0) g_cnt[b] = total;
        for (int i = total + tid; i < 1152; i += 256) g_idx[b * 1152 + i] = 0;
    }
}

// ------------------------------ K1: persistent HMMA scores ------------------
// buffer = A 32KB (2 planes of 16KB) + B 64KB (2 planes of 32KB) = 96KB; x2
#define SA_OFF 0
#define SB_OFF 32768
#define BUFSTRIDE 98304
#define SM_SMEM (2 * BUFSTRIDE)
#define K1_THREADS 512

__global__ __launch_bounds__(K1_THREADS)
void k1_mma(const float* __restrict__ enc, const float* __restrict__ Wa) {
    extern __shared__ char smem[];
    __shared__ float s_sc[128];
    const uint32_t sb = smem_u32(smem);
    const int tid = threadIdx.x;
    const int wid = tid >> 5, lid = tid & 31;
    const int bid = blockIdx.x;
    const int wm = wid & 3;
    const int wn = wid >> 2;
    const int r4 = lid >> 2, q = lid & 3;

    const uint32_t aoffb = (uint32_t)(wm * 32 + (lid & 15)) * 128u + ((lid >> 4) * 16u);
    const uint32_t boffb = (uint32_t)(wn * 64 + (lid & 7) + ((lid >> 4) << 3)) * 128u +
                           (((lid >> 3) & 1) * 16u);

    const int nunits = (NUNITS - bid + K1_GRID - 1) / K1_GRID;
    const int nsteps = nunits * 8;     // 8 double-K steps per unit

    float4 ar[4];

    // gather-load A half-piece j (kc = 2*(s&7)+j) of step s
    auto ldgA = [&](int s, int j) {
        int u = bid + (s >> 3) * K1_GRID;
        int tile = u >> 1;
        int b = tile / TPB, ti = tile - b * TPB;
        int kc = 2 * (s & 7) + j;
        const int* idxp = g_idx + b * 1152 + ti * 128;
        const float4* srcb = (const float4*)enc + (size_t)b * 2048 * 256 + kc * 16;
#pragma unroll
        for (int v = 0; v < 4; v++) {
            int i = v * K1_THREADS + tid;
            int row = i >> 4, kq = i & 15;
            int gr = idxp[row];
            ar[v] = srcb[(size_t)gr * 256 + kq];
        }
    };
    // convert + store A half-piece into buffer plane j
    auto stsA = [&](int buf, int j) {
        char* abuf = smem + buf * BUFSTRIDE + SA_OFF + j * 16384;
#pragma unroll
        for (int v = 0; v < 4; v++) {
            int i = v * K1_THREADS + tid;
            int row = i >> 4, kq = i & 15;
            float4 f = ar[v];
            uint32_t p0 = pack_half2(__float2half_rn(f.x), __float2half_rn(f.y));
            uint32_t p1 = pack_half2(__float2half_rn(f.z), __float2half_rn(f.w));
            uint32_t sw = swz((uint32_t)row * 128u + (uint32_t)kq * 8u);
            *(uint2*)(abuf + sw) = make_uint2(p0, p1);
        }
    };
    // cp.async both B half-pieces of step s into buffer
    auto cpB = [&](int s, int buf) {
        int u = bid + (s >> 3) * K1_GRID;
        int ncs = u & 1;
        int kc0 = 2 * (s & 7);
#pragma unroll
        for (int j = 0; j < 2; j++) {
            const unsigned char* srcB = g_Bt + (size_t)(ncs * 16 + kc0 + j) * 32768;
            uint32_t dst = sb + buf * BUFSTRIDE + SB_OFF + j * 32768;
#pragma unroll
            for (int v = 0; v < 4; v++)
                cp16(dst + (v * K1_THREADS + tid) * 16,
                     srcB + (size_t)(v * K1_THREADS + tid) * 16);
        }
        cp_commit();
    };

    float acc[2][8][4];
#pragma unroll
    for (int mt = 0; mt < 2; mt++)
#pragma unroll
        for (int nt = 0; nt < 8; nt++)
#pragma unroll
            for (int v = 0; v < 4; v++) acc[mt][nt][v] = 0.f;

    // prologue: fill buffer 0 with step 0
    ldgA(0, 0);
    cpB(0, 0);
    stsA(0, 0);
    ldgA(0, 1);
    stsA(0, 1);
    cp_wait0();
    __syncthreads();

    for (int s = 0; s < nsteps; s++) {
        const int cur = s & 1;
        const int u  = bid + (s >> 3) * K1_GRID;
        const int tile = u >> 1, ncs = u & 1;
        const int kc2 = s & 7;
        const uint32_t aB = sb + cur * BUFSTRIDE + SA_OFF;
        const uint32_t bB = sb + cur * BUFSTRIDE + SB_OFF;
        const bool more = (s + 1 < nsteps);

        if (more) { cpB(s + 1, cur ^ 1); ldgA(s + 1, 0); }

        // ---- MMA phase 0 (plane 0) ----
#pragma unroll
        for (int kk = 0; kk < 4; kk++) {
            uint32_t ah[2][4];
#pragma unroll
            for (int mt = 0; mt < 2; mt++) {
                uint32_t off = aoffb + (uint32_t)(mt * 16) * 128u + kk * 32u;
                ldsm4(ah[mt], aB + swz(off));
            }
#pragma unroll
            for (int ntp = 0; ntp < 4; ntp++) {
                uint32_t off = boffb + (uint32_t)(ntp * 16) * 128u + kk * 32u;
                uint32_t bh[4];
                ldsm4(bh, bB + swz(off));
#pragma unroll
                for (int mt = 0; mt < 2; mt++) {
                    mma_f16(acc[mt][2 * ntp],     ah[mt], bh[0], bh[1]);
                    mma_f16(acc[mt][2 * ntp + 1], ah[mt], bh[2], bh[3]);
                }
            }
        }

        if (more) { stsA(cur ^ 1, 0); ldgA(s + 1, 1); }

        // ---- MMA phase 1 (plane 1) ----
#pragma unroll
        for (int kk = 0; kk < 4; kk++) {
            uint32_t ah[2][4];
#pragma unroll
            for (int mt = 0; mt < 2; mt++) {
                uint32_t off = aoffb + (uint32_t)(mt * 16) * 128u + kk * 32u;
                ldsm4(ah[mt], aB + 16384 + swz(off));
            }
#pragma unroll
            for (int ntp = 0; ntp < 4; ntp++) {
                uint32_t off = boffb + (uint32_t)(ntp * 16) * 128u + kk * 32u;
                uint32_t bh[4];
                ldsm4(bh, bB + 32768 + swz(off));
#pragma unroll
                for (int mt = 0; mt < 2; mt++) {
                    mma_f16(acc[mt][2 * ntp],     ah[mt], bh[0], bh[1]);
                    mma_f16(acc[mt][2 * ntp + 1], ah[mt], bh[2], bh[3]);
                }
            }
        }

        if (more) stsA(cur ^ 1, 1);

        if (kc2 == 7) {
            const int b = tile / TPB;
            if (tid < 128) s_sc[tid] = 0.f;
            __syncthreads();
#pragma unroll
            for (int mt = 0; mt < 2; mt++) {
                float p0 = 0.f, p1 = 0.f;
#pragma unroll
                for (int nt = 0; nt < 8; nt++) {
                    int c0 = ncs * 256 + wn * 64 + nt * 8 + q * 2;
                    float d0v = g_D[b * 512 + c0], d1v = g_D[b * 512 + c0 + 1];
                    float w0 = Wa[c0], w1 = Wa[c0 + 1];
                    p0 += tanhf(acc[mt][nt][0] + d0v) * w0 + tanhf(acc[mt][nt][1] + d1v) * w1;
                    p1 += tanhf(acc[mt][nt][2] + d0v) * w0 + tanhf(acc[mt][nt][3] + d1v) * w1;
                }
                p0 += __shfl_xor_sync(0xffffffffu, p0, 1);
                p0 += __shfl_xor_sync(0xffffffffu, p0, 2);
                p1 += __shfl_xor_sync(0xffffffffu, p1, 1);
                p1 += __shfl_xor_sync(0xffffffffu, p1, 2);
                if (q == 0) {
                    atomicAdd(&s_sc[wm * 32 + mt * 16 + r4], p0);
                    atomicAdd(&s_sc[wm * 32 + mt * 16 + r4 + 8], p1);
                }
            }
            __syncthreads();
            if (tid < 128) g_sc2[ncs][tile * 128 + tid] = s_sc[tid];
#pragma unroll
            for (int mt = 0; mt < 2; mt++)
#pragma unroll
                for (int nt = 0; nt < 8; nt++)
#pragma unroll
                    for (int v = 0; v < 4; v++) acc[mt][nt][v] = 0.f;
        }

        cp_wait0();
        __syncthreads();
    }
}

// ------------------------------ k2a: compacted softmax ----------------------
__global__ void k2a_softmax() {
    int b = blockIdx.x, t = threadIdx.x;
    __shared__ float sm[1152];
    __shared__ float red[256];
    const float NEG_INF = __int_as_float(0xff800000);
    const int cnt = g_cnt[b];

    float lmax = NEG_INF;
#pragma unroll
    for (int v = 0; v < 5; v++) {
        int i = v * 256 + t;
        if (i < cnt) {
            float sc = g_sc2[0][b * 1152 + i] + g_sc2[1][b * 1152 + i];
            sm[i] = sc;
            lmax = fmaxf(lmax, sc);
        }
    }
    red[t] = lmax;
    __syncthreads();
    for (int o = 128; o > 0; o >>= 1) {
        if (t < o) red[t] = fmaxf(red[t], red[t + o]);
        __syncthreads();
    }
    float bmax = red[0];
    __syncthreads();

    float lsum = 0.f;
#pragma unroll
    for (int v = 0; v < 5; v++) {
        int i = v * 256 + t;
        if (i < cnt) {
            float e = expf(sm[i] - bmax);
            sm[i] = e;
            lsum += e;
        }
    }
    red[t] = lsum;
    __syncthreads();
    for (int o = 128; o > 0; o >>= 1) {
        if (t < o) red[t] += red[t + o];
        __syncthreads();
    }
    float inv = 1.f / red[0];
#pragma unroll
    for (int v = 0; v < 5; v++) {
        int i = v * 256 + t;
        if (i < 1152) g_wc[b * 1152 + i] = (i < cnt) ? sm[i] * inv : 0.f;
    }
}

// ------------------------------ k2b: gathered weighted sum ------------------
__global__ void k2b_partial(const float* __restrict__ enc) {
    int ch = blockIdx.x, b = blockIdx.y, t = threadIdx.x;
    __shared__ float wv[128];
    __shared__ int   sidx[128];

    if (t < 128) {
        wv[t]   = g_wc[b * 1152 + ch * 128 + t];
        sidx[t] = g_idx[b * 1152 + ch * 128 + t];
    }
    __syncthreads();

    const float4* rowbase = (const float4*)enc + (size_t)b * 2048 * 256;
    float4 acc = make_float4(0.f, 0.f, 0.f, 0.f);
#pragma unroll 1
    for (int i = 0; i < 128; i += 4) {
        int i0 = sidx[i], i1 = sidx[i + 1], i2 = sidx[i + 2], i3 = sidx[i + 3];
        float w0 = wv[i], w1 = wv[i + 1], w2 = wv[i + 2], w3 = wv[i + 3];
        float4 v0 = rowbase[(size_t)i0 * 256 + t];
        float4 v1 = rowbase[(size_t)i1 * 256 + t];
        float4 v2 = rowbase[(size_t)i2 * 256 + t];
        float4 v3 = rowbase[(size_t)i3 * 256 + t];
        acc.x += w0 * v0.x + w1 * v1.x + w2 * v2.x + w3 * v3.x;
        acc.y += w0 * v0.y + w1 * v1.y + w2 * v2.y + w3 * v3.y;
        acc.z += w0 * v0.z + w1 * v1.z + w2 * v2.z + w3 * v3.z;
        acc.w += w0 * v0.w + w1 * v1.w + w2 * v2.w + w3 * v3.w;
    }
    reinterpret_cast<float4*>(g_partial)[(b * NCHUNK + ch) * 256 + t] = acc;
}

// ------------------------------ k2c: final GEMV -----------------------------
__global__ void k2c_context(const float* __restrict__ We,
                            const float* __restrict__ be,
                            float* __restrict__ out) {
    int b = blockIdx.x, t = threadIdx.x;
    __shared__ float ctx[1024];
    float4 s = make_float4(0.f, 0.f, 0.f, 0.f);
#pragma unroll
    for (int chn = 0; chn < NCHUNK; chn++) {
        float4 v = reinterpret_cast<const float4*>(g_partial)[(b * NCHUNK + chn) * 256 + t];
        s.x += v.x; s.y += v.y; s.z += v.z; s.w += v.w;
    }
    reinterpret_cast<float4*>(ctx)[t] = s;
    __syncthreads();

    float acc0 = be[t], acc1 = be[t + 256];
#pragma unroll 4
    for (int k = 0; k < 1024; k++) {
        float c = ctx[k];
        const float* wr = We + k * 512;
        acc0 += c * wr[t];
        acc1 += c * wr[t + 256];
    }
    out[b * 512 + t]       = acc0;
    out[b * 512 + t + 256] = acc1;
}

// ---------------------------------------------------------------------------
extern "C" void kernel_launch(void* const* d_in, const int* in_sizes, int n_in,
                              void* d_out, int out_size) {
    const float*         enc   = (const float*)d_in[0];
    const float*         dec   = (const float*)d_in[1];
    const unsigned char* masks = (const unsigned char*)d_in[2];
    const float*         We    = (const float*)d_in[3];
    const float*         be    = (const float*)d_in[4];
    const float*         Wd    = (const float*)d_in[5];
    const float*         bd    = (const float*)d_in[6];
    const float*         Wa    = (const float*)d_in[7];
    float* out = (float*)d_out;

    static int configured = 0;
    if (!configured) {
        cudaFuncSetAttribute(k1_mma, cudaFuncAttributeMaxDynamicSharedMemorySize, SM_SMEM);
        configured = 1;
    }

    k_prep<<<2144, 256>>>(We, dec, Wd, bd, be, masks);
    k1_mma<<<K1_GRID, K1_THREADS, SM_SMEM>>>(enc, Wa);
    k2a_softmax<<<Bn, 256>>>();
    dim3 g2b(NCHUNK, Bn);
    k2b_partial<<<g2b, 256>>>(enc);
    k2c_context<<<Bn, 256>>>(We, be, out);
}

// round 17
// speedup vs baseline: 2.7464x; 1.0470x over previous
#include <cuda_runtime.h>
#include <cuda_fp16.h>
#include <math.h>
#include <stdint.h>

#define Bn 32
#define Sn 2048
#define NCHUNK 18             // compacted chunks of 64 rows (capacity 1152)
#define TPB 9                 // k1 tiles per batch
#define NUNITS (Bn * TPB * 2) // 576 (tile, nc) units
#define K1_GRID 148

// ------------------------------ device scratch ------------------------------
__device__ float g_D[Bn * 512];
__device__ float g_sc2[2][Bn * 1152];   // per-nc compacted score partials
__device__ float g_wc[Bn * 1152];       // compacted softmax weights
__device__ float g_partial[Bn * NCHUNK * 1024];
__device__ int   g_idx[Bn * 1152];      // compacted unmasked row indices
__device__ int   g_cnt[Bn];
// W_enc staged as fp16, SW128-swizzled [n][k] tiles. 32 pieces, each 32KB
__device__ __align__(16) unsigned char g_Bt[32 * 32768];

// ------------------------------ helpers -------------------------------------
__device__ __forceinline__ uint32_t smem_u32(const void* p) {
    uint32_t a;
    asm("{ .reg .u64 t; cvta.to.shared.u64 t, %1; cvt.u32.u64 %0, t; }"
        : "=r"(a) : "l"(p));
    return a;
}
__device__ __forceinline__ uint32_t swz(uint32_t off) {
    return off ^ ((off >> 3) & 0x70);
}
__device__ __forceinline__ void ldsm4(uint32_t* r, uint32_t addr) {
    asm volatile("ldmatrix.sync.aligned.m8n8.x4.shared.b16 {%0,%1,%2,%3}, [%4];"
                 : "=r"(r[0]), "=r"(r[1]), "=r"(r[2]), "=r"(r[3]) : "r"(addr));
}
__device__ __forceinline__ void mma_f16(float* c, const uint32_t* a,
                                        uint32_t b0, uint32_t b1) {
    asm("mma.sync.aligned.m16n8k16.row.col.f32.f16.f16.f32 "
        "{%0,%1,%2,%3},{%4,%5,%6,%7},{%8,%9},{%0,%1,%2,%3};"
        : "+f"(c[0]), "+f"(c[1]), "+f"(c[2]), "+f"(c[3])
        : "r"(a[0]), "r"(a[1]), "r"(a[2]), "r"(a[3]), "r"(b0), "r"(b1));
}
__device__ __forceinline__ void cp16(uint32_t dst, const void* src) {
    asm volatile("cp.async.cg.shared.global [%0], [%1], 16;"
                 :: "r"(dst), "l"(src));
}
__device__ __forceinline__ void cp_commit() {
    asm volatile("cp.async.commit_group;" ::: "memory");
}
__device__ __forceinline__ void cp_wait0() {
    asm volatile("cp.async.wait_group 0;" ::: "memory");
}
__device__ __forceinline__ uint32_t pack_half2(__half a, __half b) {
    __half2 h = __halves2half2(a, b);
    return *(uint32_t*)&h;
}

// ------------------------------ k_prep --------------------------------------
// blocks [0,2048): kW staging; [2048,2112): k0 decoder; [2112,2144): compaction
__global__ __launch_bounds__(256)
void k_prep(const float* __restrict__ We, const float* __restrict__ dec,
            const float* __restrict__ Wd, const float* __restrict__ bd,
            const float* __restrict__ be, const unsigned char* __restrict__ masks) {
    __shared__ float ds[512];
    __shared__ int   wsum[8];
    const int bi = blockIdx.x, tid = threadIdx.x;

    if (bi < 2048) {
        int gid = bi * 256 + tid;
        int k = gid >> 9, n = gid & 511;
        __half hw = __float2half_rn(We[gid]);
        int kc = k >> 6, kl = k & 63, nc = n >> 8, nl = n & 255;
        int piece = nc * 16 + kc;
        uint32_t sw = swz((uint32_t)nl * 128u + (uint32_t)kl * 2u);
        *(__half*)(g_Bt + (size_t)piece * 32768 + sw) = hw;
    } else if (bi < 2112) {
        int idx = bi - 2048;
        int b = idx >> 1, ah = idx & 1;
        ds[tid]       = dec[b * 512 + tid];
        ds[tid + 256] = dec[b * 512 + tid + 256];
        __syncthreads();
        int a = ah * 256 + tid;
        float acc = be[a] + bd[a];
#pragma unroll 8
        for (int h = 0; h < 512; h++) acc += ds[h] * Wd[h * 512 + a];
        g_D[b * 512 + a] = acc;
    } else {
        int b = bi - 2112;
        int found = 0;
        for (int j = tid; j < 16384; j += 256)
            if (masks[4 * j + 1]) found = 1;
        const int mode = __syncthreads_or(found); // 1 = byte elems, 0 = 4-byte
        const unsigned int* m32 = (const unsigned int*)masks;

        int keep[8], c = 0;
#pragma unroll
        for (int j = 0; j < 8; j++) {
            int i = tid * 8 + j;
            bool masked = mode ? (masks[b * 2048 + i] != 0)
                               : (m32[b * 2048 + i] != 0u);
            keep[j] = masked ? 0 : 1;
            c += keep[j];
        }
        int lane = tid & 31, w = tid >> 5;
        int incl = c;
#pragma unroll
        for (int o = 1; o < 32; o <<= 1) {
            int v = __shfl_up_sync(0xffffffffu, incl, o);
            if (lane >= o) incl += v;
        }
        if (lane == 31) wsum[w] = incl;
        __syncthreads();
        int woff = 0;
#pragma unroll
        for (int ww = 0; ww < 8; ww++) if (ww < w) woff += wsum[ww];
        int pos = woff + incl - c;
        int total = 0;
#pragma unroll
        for (int ww = 0; ww < 8; ww++) total += wsum[ww];
#pragma unroll
        for (int j = 0; j < 8; j++) {
            if (keep[j]) g_idx[b * 1152 + pos++] = tid * 8 + j;
        }
        if (tid == 0) g_cnt[b] = total;
        for (int i = total + tid; i < 1152; i += 256) g_idx[b * 1152 + i] = 0;
    }
}

// ------------------------------ K1: persistent HMMA scores ------------------
// buffer = A 32KB (2 planes of 16KB) + B 64KB (2 planes of 32KB) = 96KB; x2
#define SA_OFF 0
#define SB_OFF 32768
#define BUFSTRIDE 98304
#define SM_SMEM (2 * BUFSTRIDE)
#define K1_THREADS 512

__global__ __launch_bounds__(K1_THREADS)
void k1_mma(const float* __restrict__ enc, const float* __restrict__ Wa) {
    extern __shared__ char smem[];
    __shared__ float s_sc[128];
    const uint32_t sb = smem_u32(smem);
    const int tid = threadIdx.x;
    const int wid = tid >> 5, lid = tid & 31;
    const int bid = blockIdx.x;
    const int wm = wid & 3;
    const int wn = wid >> 2;
    const int r4 = lid >> 2, q = lid & 3;

    const uint32_t aoffb = (uint32_t)(wm * 32 + (lid & 15)) * 128u + ((lid >> 4) * 16u);
    const uint32_t boffb = (uint32_t)(wn * 64 + (lid & 7) + ((lid >> 4) << 3)) * 128u +
                           (((lid >> 3) & 1) * 16u);

    const int nunits = (NUNITS - bid + K1_GRID - 1) / K1_GRID;
    const int nsteps = nunits * 8;     // 8 double-K steps per unit

    float4 ar[4];

    auto ldgA = [&](int s, int j) {
        int u = bid + (s >> 3) * K1_GRID;
        int tile = u >> 1;
        int b = tile / TPB, ti = tile - b * TPB;
        int kc = 2 * (s & 7) + j;
        const int* idxp = g_idx + b * 1152 + ti * 128;
        const float4* srcb = (const float4*)enc + (size_t)b * 2048 * 256 + kc * 16;
#pragma unroll
        for (int v = 0; v < 4; v++) {
            int i = v * K1_THREADS + tid;
            int row = i >> 4, kq = i & 15;
            int gr = idxp[row];
            ar[v] = srcb[(size_t)gr * 256 + kq];
        }
    };
    auto stsA = [&](int buf, int j) {
        char* abuf = smem + buf * BUFSTRIDE + SA_OFF + j * 16384;
#pragma unroll
        for (int v = 0; v < 4; v++) {
            int i = v * K1_THREADS + tid;
            int row = i >> 4, kq = i & 15;
            float4 f = ar[v];
            uint32_t p0 = pack_half2(__float2half_rn(f.x), __float2half_rn(f.y));
            uint32_t p1 = pack_half2(__float2half_rn(f.z), __float2half_rn(f.w));
            uint32_t sw = swz((uint32_t)row * 128u + (uint32_t)kq * 8u);
            *(uint2*)(abuf + sw) = make_uint2(p0, p1);
        }
    };
    auto cpB = [&](int s, int buf) {
        int u = bid + (s >> 3) * K1_GRID;
        int ncs = u & 1;
        int kc0 = 2 * (s & 7);
#pragma unroll
        for (int j = 0; j < 2; j++) {
            const unsigned char* srcB = g_Bt + (size_t)(ncs * 16 + kc0 + j) * 32768;
            uint32_t dst = sb + buf * BUFSTRIDE + SB_OFF + j * 32768;
#pragma unroll
            for (int v = 0; v < 4; v++)
                cp16(dst + (v * K1_THREADS + tid) * 16,
                     srcB + (size_t)(v * K1_THREADS + tid) * 16);
        }
        cp_commit();
    };

    float acc[2][8][4];
#pragma unroll
    for (int mt = 0; mt < 2; mt++)
#pragma unroll
        for (int nt = 0; nt < 8; nt++)
#pragma unroll
            for (int v = 0; v < 4; v++) acc[mt][nt][v] = 0.f;

    // prologue: fill buffer 0 with step 0
    ldgA(0, 0);
    cpB(0, 0);
    stsA(0, 0);
    ldgA(0, 1);
    stsA(0, 1);
    cp_wait0();
    __syncthreads();

    for (int s = 0; s < nsteps; s++) {
        const int cur = s & 1;
        const int u  = bid + (s >> 3) * K1_GRID;
        const int tile = u >> 1, ncs = u & 1;
        const int kc2 = s & 7;
        const uint32_t aB = sb + cur * BUFSTRIDE + SA_OFF;
        const uint32_t bB = sb + cur * BUFSTRIDE + SB_OFF;
        const bool more = (s + 1 < nsteps);

        if (more) { cpB(s + 1, cur ^ 1); ldgA(s + 1, 0); }

        // ---- MMA phase 0 (plane 0) ----
#pragma unroll
        for (int kk = 0; kk < 4; kk++) {
            uint32_t ah[2][4];
#pragma unroll
            for (int mt = 0; mt < 2; mt++) {
                uint32_t off = aoffb + (uint32_t)(mt * 16) * 128u + kk * 32u;
                ldsm4(ah[mt], aB + swz(off));
            }
#pragma unroll
            for (int ntp = 0; ntp < 4; ntp++) {
                uint32_t off = boffb + (uint32_t)(ntp * 16) * 128u + kk * 32u;
                uint32_t bh[4];
                ldsm4(bh, bB + swz(off));
#pragma unroll
                for (int mt = 0; mt < 2; mt++) {
                    mma_f16(acc[mt][2 * ntp],     ah[mt], bh[0], bh[1]);
                    mma_f16(acc[mt][2 * ntp + 1], ah[mt], bh[2], bh[3]);
                }
            }
        }

        if (more) { stsA(cur ^ 1, 0); ldgA(s + 1, 1); }

        // ---- MMA phase 1 (plane 1) ----
#pragma unroll
        for (int kk = 0; kk < 4; kk++) {
            uint32_t ah[2][4];
#pragma unroll
            for (int mt = 0; mt < 2; mt++) {
                uint32_t off = aoffb + (uint32_t)(mt * 16) * 128u + kk * 32u;
                ldsm4(ah[mt], aB + 16384 + swz(off));
            }
#pragma unroll
            for (int ntp = 0; ntp < 4; ntp++) {
                uint32_t off = boffb + (uint32_t)(ntp * 16) * 128u + kk * 32u;
                uint32_t bh[4];
                ldsm4(bh, bB + 32768 + swz(off));
#pragma unroll
                for (int mt = 0; mt < 2; mt++) {
                    mma_f16(acc[mt][2 * ntp],     ah[mt], bh[0], bh[1]);
                    mma_f16(acc[mt][2 * ntp + 1], ah[mt], bh[2], bh[3]);
                }
            }
        }

        if (more) stsA(cur ^ 1, 1);

        if (kc2 == 7) {
            const int b = tile / TPB;
            if (tid < 128) s_sc[tid] = 0.f;
            __syncthreads();
#pragma unroll
            for (int mt = 0; mt < 2; mt++) {
                float p0 = 0.f, p1 = 0.f;
#pragma unroll
                for (int nt = 0; nt < 8; nt++) {
                    int c0 = ncs * 256 + wn * 64 + nt * 8 + q * 2;
                    float d0v = g_D[b * 512 + c0], d1v = g_D[b * 512 + c0 + 1];
                    float w0 = Wa[c0], w1 = Wa[c0 + 1];
                    p0 += tanhf(acc[mt][nt][0] + d0v) * w0 + tanhf(acc[mt][nt][1] + d1v) * w1;
                    p1 += tanhf(acc[mt][nt][2] + d0v) * w0 + tanhf(acc[mt][nt][3] + d1v) * w1;
                }
                p0 += __shfl_xor_sync(0xffffffffu, p0, 1);
                p0 += __shfl_xor_sync(0xffffffffu, p0, 2);
                p1 += __shfl_xor_sync(0xffffffffu, p1, 1);
                p1 += __shfl_xor_sync(0xffffffffu, p1, 2);
                if (q == 0) {
                    atomicAdd(&s_sc[wm * 32 + mt * 16 + r4], p0);
                    atomicAdd(&s_sc[wm * 32 + mt * 16 + r4 + 8], p1);
                }
            }
            __syncthreads();
            if (tid < 128) g_sc2[ncs][tile * 128 + tid] = s_sc[tid];
#pragma unroll
            for (int mt = 0; mt < 2; mt++)
#pragma unroll
                for (int nt = 0; nt < 8; nt++)
#pragma unroll
                    for (int v = 0; v < 4; v++) acc[mt][nt][v] = 0.f;
        }

        cp_wait0();
        __syncthreads();
    }
}

// ------------------------------ k2a: compacted softmax ----------------------
__global__ void k2a_softmax() {
    int b = blockIdx.x, t = threadIdx.x;
    __shared__ float sm[1152];
    __shared__ float red[256];
    const float NEG_INF = __int_as_float(0xff800000);
    const int cnt = g_cnt[b];

    float lmax = NEG_INF;
#pragma unroll
    for (int v = 0; v < 5; v++) {
        int i = v * 256 + t;
        if (i < cnt) {
            float sc = g_sc2[0][b * 1152 + i] + g_sc2[1][b * 1152 + i];
            sm[i] = sc;
            lmax = fmaxf(lmax, sc);
        }
    }
    red[t] = lmax;
    __syncthreads();
    for (int o = 128; o > 0; o >>= 1) {
        if (t < o) red[t] = fmaxf(red[t], red[t + o]);
        __syncthreads();
    }
    float bmax = red[0];
    __syncthreads();

    float lsum = 0.f;
#pragma unroll
    for (int v = 0; v < 5; v++) {
        int i = v * 256 + t;
        if (i < cnt) {
            float e = expf(sm[i] - bmax);
            sm[i] = e;
            lsum += e;
        }
    }
    red[t] = lsum;
    __syncthreads();
    for (int o = 128; o > 0; o >>= 1) {
        if (t < o) red[t] += red[t + o];
        __syncthreads();
    }
    float inv = 1.f / red[0];
#pragma unroll
    for (int v = 0; v < 5; v++) {
        int i = v * 256 + t;
        if (i < 1152) g_wc[b * 1152 + i] = (i < cnt) ? sm[i] * inv : 0.f;
    }
}

// ------------------------------ k2b: gathered weighted sum (64-row chunks) --
__global__ void k2b_partial(const float* __restrict__ enc) {
    int ch = blockIdx.x, b = blockIdx.y, t = threadIdx.x;
    __shared__ float wv[64];
    __shared__ int   sidx[64];

    if (t < 64) {
        wv[t]   = g_wc[b * 1152 + ch * 64 + t];
        sidx[t] = g_idx[b * 1152 + ch * 64 + t];
    }
    __syncthreads();

    const float4* rowbase = (const float4*)enc + (size_t)b * 2048 * 256;
    float4 acc = make_float4(0.f, 0.f, 0.f, 0.f);
#pragma unroll 1
    for (int i = 0; i < 64; i += 4) {
        int i0 = sidx[i], i1 = sidx[i + 1], i2 = sidx[i + 2], i3 = sidx[i + 3];
        float w0 = wv[i], w1 = wv[i + 1], w2 = wv[i + 2], w3 = wv[i + 3];
        float4 v0 = rowbase[(size_t)i0 * 256 + t];
        float4 v1 = rowbase[(size_t)i1 * 256 + t];
        float4 v2 = rowbase[(size_t)i2 * 256 + t];
        float4 v3 = rowbase[(size_t)i3 * 256 + t];
        acc.x += w0 * v0.x + w1 * v1.x + w2 * v2.x + w3 * v3.x;
        acc.y += w0 * v0.y + w1 * v1.y + w2 * v2.y + w3 * v3.y;
        acc.z += w0 * v0.z + w1 * v1.z + w2 * v2.z + w3 * v3.z;
        acc.w += w0 * v0.w + w1 * v1.w + w2 * v2.w + w3 * v3.w;
    }
    reinterpret_cast<float4*>(g_partial)[(b * NCHUNK + ch) * 256 + t] = acc;
}

// ------------------------------ k2c: final GEMV -----------------------------
__global__ void k2c_context(const float* __restrict__ We,
                            const float* __restrict__ be,
                            float* __restrict__ out) {
    int b = blockIdx.x, t = threadIdx.x;
    __shared__ float ctx[1024];
    float4 s = make_float4(0.f, 0.f, 0.f, 0.f);
#pragma unroll
    for (int chn = 0; chn < NCHUNK; chn++) {
        float4 v = reinterpret_cast<const float4*>(g_partial)[(b * NCHUNK + chn) * 256 + t];
        s.x += v.x; s.y += v.y; s.z += v.z; s.w += v.w;
    }
    reinterpret_cast<float4*>(ctx)[t] = s;
    __syncthreads();

    float acc0 = be[t], acc1 = be[t + 256];
#pragma unroll 4
    for (int k = 0; k < 1024; k++) {
        float c = ctx[k];
        const float* wr = We + k * 512;
        acc0 += c * wr[t];
        acc1 += c * wr[t + 256];
    }
    out[b * 512 + t]       = acc0;
    out[b * 512 + t + 256] = acc1;
}

// ---------------------------------------------------------------------------
extern "C" void kernel_launch(void* const* d_in, const int* in_sizes, int n_in,
                              void* d_out, int out_size) {
    const float*         enc   = (const float*)d_in[0];
    const float*         dec   = (const float*)d_in[1];
    const unsigned char* masks = (const unsigned char*)d_in[2];
    const float*         We    = (const float*)d_in[3];
    const float*         be    = (const float*)d_in[4];
    const float*         Wd    = (const float*)d_in[5];
    const float*         bd    = (const float*)d_in[6];
    const float*         Wa    = (const float*)d_in[7];
    float* out = (float*)d_out;

    static int configured = 0;
    if (!configured) {
        cudaFuncSetAttribute(k1_mma, cudaFuncAttributeMaxDynamicSharedMemorySize, SM_SMEM);
        configured = 1;
    }

    k_prep<<<2144, 256>>>(We, dec, Wd, bd, be, masks);
    k1_mma<<<K1_GRID, K1_THREADS, SM_SMEM>>>(enc, Wa);
    k2a_softmax<<<Bn, 256>>>();
    dim3 g2b(NCHUNK, Bn);
    k2b_partial<<<g2b, 256>>>(enc);
    k2c_context<<<Bn, 256>>>(We, be, out);
}